// round 1
// baseline (speedup 1.0000x reference)
#include <cuda_runtime.h>
#include <math.h>

// ---------------- scratch (static device globals; no allocation) ------------
__device__ float g_h[8 * 512 * 1024];      // groupnorm output   [b,c,t]
__device__ float g_qkv[8 * 1536 * 1024];   // qkv projection     [b,3c,t]
__device__ float g_a[8 * 512 * 1024];      // attention output   [b,c,t]

// ---------------- GroupNorm -------------------------------------------------
// One block per (b, group). 16 channels x 1024 = 16384 elems per group.
__global__ void groupnorm_kernel(const float* __restrict__ x,
                                 const float* __restrict__ gamma,
                                 const float* __restrict__ beta,
                                 float* __restrict__ out) {
    int b = blockIdx.x >> 5;
    int g = blockIdx.x & 31;
    const float* xp = x + ((size_t)b * 512 + g * 16) * 1024;
    float* op = out + ((size_t)b * 512 + g * 16) * 1024;
    int tid = threadIdx.x;

    float s = 0.f, ss = 0.f;
    for (int e = tid; e < 16 * 1024; e += 256) {
        float v = xp[e];
        s += v; ss += v * v;
    }
    __shared__ float rs[256], rss[256];
    rs[tid] = s; rss[tid] = ss;
    __syncthreads();
    for (int o = 128; o > 0; o >>= 1) {
        if (tid < o) { rs[tid] += rs[tid + o]; rss[tid] += rss[tid + o]; }
        __syncthreads();
    }
    float mean = rs[0] * (1.f / 16384.f);
    float var  = rss[0] * (1.f / 16384.f) - mean * mean;
    float inv  = rsqrtf(var + 1e-5f);

    for (int e = tid; e < 16 * 1024; e += 256) {
        int cl = e >> 10;
        float v = (xp[e] - mean) * inv;
        op[e] = v * gamma[g * 16 + cl] + beta[g * 16 + cl];
    }
}

// ---------------- GEMM: C[b] = W (MxK) @ B[b] (Kx1024) + bias (+resid) ------
// 64x64 block tile, BK=16, 256 threads, 4x4 per thread.
__global__ void gemm_kernel(const float* __restrict__ W,
                            const float* __restrict__ Bmat,
                            const float* __restrict__ bias,
                            const float* __restrict__ resid,
                            float* __restrict__ Cout,
                            int M, int Kdim) {
    __shared__ float As[16][64];
    __shared__ float Bs[16][64];

    int bz = blockIdx.z;
    const float* Bp = Bmat + (size_t)bz * Kdim * 1024;
    float* Cp = Cout + (size_t)bz * M * 1024;
    const float* Rp = resid ? resid + (size_t)bz * M * 1024 : nullptr;

    int m0 = blockIdx.y * 64, n0 = blockIdx.x * 64;
    int tid = threadIdx.x;
    int ty = tid >> 4, tx = tid & 15;

    int lm  = tid >> 2;          // 0..63 : W row within tile
    int lk4 = (tid & 3) * 4;     // 0,4,8,12
    int bk  = tid >> 4;          // 0..15 : B row within tile
    int bn4 = (tid & 15) * 4;    // 0..60

    float acc[4][4] = {};

    for (int k0 = 0; k0 < Kdim; k0 += 16) {
        float4 w4 = *(const float4*)&W[(size_t)(m0 + lm) * Kdim + k0 + lk4];
        As[lk4 + 0][lm] = w4.x;
        As[lk4 + 1][lm] = w4.y;
        As[lk4 + 2][lm] = w4.z;
        As[lk4 + 3][lm] = w4.w;
        *(float4*)&Bs[bk][bn4] =
            *(const float4*)&Bp[(size_t)(k0 + bk) * 1024 + n0 + bn4];
        __syncthreads();

#pragma unroll
        for (int k = 0; k < 16; k++) {
            float4 a4 = *(const float4*)&As[k][ty * 4];
            float4 b4 = *(const float4*)&Bs[k][tx * 4];
            float av[4] = {a4.x, a4.y, a4.z, a4.w};
            float bv[4] = {b4.x, b4.y, b4.z, b4.w};
#pragma unroll
            for (int i = 0; i < 4; i++)
#pragma unroll
                for (int j = 0; j < 4; j++)
                    acc[i][j] = fmaf(av[i], bv[j], acc[i][j]);
        }
        __syncthreads();
    }

#pragma unroll
    for (int i = 0; i < 4; i++) {
        int m = m0 + ty * 4 + i;
        float bv = bias[m];
        size_t off = (size_t)m * 1024 + n0 + tx * 4;
        float4 r;
        r.x = acc[i][0] + bv; r.y = acc[i][1] + bv;
        r.z = acc[i][2] + bv; r.w = acc[i][3] + bv;
        if (Rp) {
            float4 rr = *(const float4*)&Rp[off];
            r.x += rr.x; r.y += rr.y; r.z += rr.z; r.w += rr.w;
        }
        *(float4*)&Cp[off] = r;
    }
}

// ---------------- Attention (flash-style, 64 t-rows per block) --------------
// qkv: [b, 8 heads * 192, 1024]; per head: q rows [0,64), k [64,128), v [128,192)
// scores S[t][s] = 0.125 * sum_c q[c][t] k[c][s]; softmax over s; O[t][c] = sum_s P V[c][s]
extern __shared__ float attn_smem[];
__global__ void attn_kernel(const float* __restrict__ qkv,
                            float* __restrict__ aout) {
    float* Qs = attn_smem;            // [64][64]  Q (scaled), [c][t]
    float* KP = Qs + 64 * 64;         // [64][68]  K ([c][s]) then P ([t][s])
    float* Vt = KP + 64 * 68;         // [64][68]  V transposed [s][c]

    int bh = blockIdx.y;
    int b = bh >> 3, h = bh & 7;
    const float* base = qkv + ((size_t)b * 1536 + h * 192) * 1024;
    const float* Qp = base;
    const float* Kp = base + 64 * 1024;
    const float* Vp = base + 128 * 1024;
    int t0 = blockIdx.x * 64;

    int tid = threadIdx.x;
    int ty = tid >> 4, tx = tid & 15;

    // load Q tile (scaled by 1/8 = scale^2)
    for (int it = 0; it < 4; it++) {
        int idx = tid + it * 256;               // 0..1023 float4 slots
        int c = idx >> 4;
        int t4 = (idx & 15) * 4;
        float4 v = *(const float4*)&Qp[(size_t)c * 1024 + t0 + t4];
        v.x *= 0.125f; v.y *= 0.125f; v.z *= 0.125f; v.w *= 0.125f;
        *(float4*)&Qs[c * 64 + t4] = v;
    }

    float O[4][4] = {};
    float mrow[4] = {-INFINITY, -INFINITY, -INFINITY, -INFINITY};
    float lrow[4] = {};

    for (int s0 = 0; s0 < 1024; s0 += 64) {
        __syncthreads();   // previous iter's smem reads done (also covers Q load)

        // load K tile [c][s] and V tile transposed [s][c]
        for (int it = 0; it < 4; it++) {
            int idx = tid + it * 256;
            int c = idx >> 4;
            int s4 = (idx & 15) * 4;
            float4 kv = *(const float4*)&Kp[(size_t)c * 1024 + s0 + s4];
            *(float4*)&KP[c * 68 + s4] = kv;
            float4 vv = *(const float4*)&Vp[(size_t)c * 1024 + s0 + s4];
            Vt[(s4 + 0) * 68 + c] = vv.x;
            Vt[(s4 + 1) * 68 + c] = vv.y;
            Vt[(s4 + 2) * 68 + c] = vv.z;
            Vt[(s4 + 3) * 68 + c] = vv.w;
        }
        __syncthreads();

        // S tile: rows ty*4+i, cols tx*4+j
        float S[4][4] = {};
#pragma unroll 8
        for (int c = 0; c < 64; c++) {
            float4 q4 = *(const float4*)&Qs[c * 64 + ty * 4];
            float4 k4 = *(const float4*)&KP[c * 68 + tx * 4];
            float qv[4] = {q4.x, q4.y, q4.z, q4.w};
            float kv[4] = {k4.x, k4.y, k4.z, k4.w};
#pragma unroll
            for (int i = 0; i < 4; i++)
#pragma unroll
                for (int j = 0; j < 4; j++)
                    S[i][j] = fmaf(qv[i], kv[j], S[i][j]);
        }

        // online softmax per row (reduce across 16 tx lanes via shfl)
#pragma unroll
        for (int i = 0; i < 4; i++) {
            float mx = fmaxf(fmaxf(S[i][0], S[i][1]), fmaxf(S[i][2], S[i][3]));
#pragma unroll
            for (int off = 8; off > 0; off >>= 1)
                mx = fmaxf(mx, __shfl_xor_sync(0xffffffffu, mx, off));
            float mnew = fmaxf(mrow[i], mx);
            float corr = __expf(mrow[i] - mnew);
            float rsum = 0.f;
#pragma unroll
            for (int j = 0; j < 4; j++) {
                float p = __expf(S[i][j] - mnew);
                S[i][j] = p;
                rsum += p;
            }
#pragma unroll
            for (int off = 8; off > 0; off >>= 1)
                rsum += __shfl_xor_sync(0xffffffffu, rsum, off);
            lrow[i] = lrow[i] * corr + rsum;
            mrow[i] = mnew;
#pragma unroll
            for (int j = 0; j < 4; j++) O[i][j] *= corr;
        }

        __syncthreads();   // everyone done reading K from KP

        // store P into KP: [t][s], row stride 68
#pragma unroll
        for (int i = 0; i < 4; i++)
            *(float4*)&KP[(ty * 4 + i) * 68 + tx * 4] =
                make_float4(S[i][0], S[i][1], S[i][2], S[i][3]);
        __syncthreads();

        // O[t][c] += P[t][s] * Vt[s][c] ; rows t = ty*4+i, cols c = tx*4+j
#pragma unroll 8
        for (int s = 0; s < 64; s++) {
            float4 v4 = *(const float4*)&Vt[s * 68 + tx * 4];
            float vv[4] = {v4.x, v4.y, v4.z, v4.w};
#pragma unroll
            for (int i = 0; i < 4; i++) {
                float p = KP[(ty * 4 + i) * 68 + s];
#pragma unroll
                for (int j = 0; j < 4; j++)
                    O[i][j] = fmaf(p, vv[j], O[i][j]);
            }
        }
    }

    // normalize and transpose through smem for coalesced [c][t] writes
    __syncthreads();
#pragma unroll
    for (int i = 0; i < 4; i++) {
        float invl = 1.f / lrow[i];
#pragma unroll
        for (int j = 0; j < 4; j++)
            Vt[(tx * 4 + j) * 68 + ty * 4 + i] = O[i][j] * invl;
    }
    __syncthreads();
    float* ap = aout + ((size_t)b * 512 + h * 64) * 1024;
    for (int it = 0; it < 4; it++) {
        int idx = tid + it * 256;
        int c = idx >> 4;
        int t4 = (idx & 15) * 4;
        *(float4*)&ap[(size_t)c * 1024 + t0 + t4] =
            *(const float4*)&Vt[c * 68 + t4];
    }
}

// ---------------- launch ----------------------------------------------------
extern "C" void kernel_launch(void* const* d_in, const int* in_sizes, int n_in,
                              void* d_out, int out_size) {
    const float* x      = (const float*)d_in[0];
    const float* gamma  = (const float*)d_in[1];
    const float* beta   = (const float*)d_in[2];
    const float* w_qkv  = (const float*)d_in[3];
    const float* b_qkv  = (const float*)d_in[4];
    const float* w_proj = (const float*)d_in[5];
    const float* b_proj = (const float*)d_in[6];
    float* out = (float*)d_out;

    float *h_ptr, *qkv_ptr, *a_ptr;
    cudaGetSymbolAddress((void**)&h_ptr, g_h);
    cudaGetSymbolAddress((void**)&qkv_ptr, g_qkv);
    cudaGetSymbolAddress((void**)&a_ptr, g_a);

    // 1) GroupNorm
    groupnorm_kernel<<<8 * 32, 256>>>(x, gamma, beta, h_ptr);

    // 2) QKV GEMM: [1536,512] @ [512,1024] per batch
    gemm_kernel<<<dim3(16, 24, 8), 256>>>(w_qkv, h_ptr, b_qkv, nullptr,
                                          qkv_ptr, 1536, 512);

    // 3) Attention
    cudaFuncSetAttribute(attn_kernel,
                         cudaFuncAttributeMaxDynamicSharedMemorySize, 51200);
    attn_kernel<<<dim3(16, 64), 256, 51200>>>(qkv_ptr, a_ptr);

    // 4) Proj GEMM + bias + residual
    gemm_kernel<<<dim3(16, 8, 8), 256>>>(w_proj, a_ptr, b_proj, x,
                                         out, 512, 512);
}

// round 2
// speedup vs baseline: 1.4703x; 1.4703x over previous
#include <cuda_runtime.h>
#include <math.h>
#include <stdint.h>

// ---------------- scratch (static device globals; no allocation) ------------
__device__ float g_h[8 * 512 * 1024];      // groupnorm output   [b,c,t]
__device__ float g_qkv[8 * 1536 * 1024];   // qkv projection     [b,3c,t]
__device__ float g_a[8 * 512 * 1024];      // attention output   [b,c,t]

// ---------------- GroupNorm -------------------------------------------------
__global__ void groupnorm_kernel(const float* __restrict__ x,
                                 const float* __restrict__ gamma,
                                 const float* __restrict__ beta,
                                 float* __restrict__ out) {
    int b = blockIdx.x >> 5;
    int g = blockIdx.x & 31;
    const float* xp = x + ((size_t)b * 512 + g * 16) * 1024;
    float* op = out + ((size_t)b * 512 + g * 16) * 1024;
    int tid = threadIdx.x;

    float s = 0.f, ss = 0.f;
    for (int e = tid; e < 16 * 1024; e += 256) {
        float v = xp[e];
        s += v; ss += v * v;
    }
    __shared__ float rs[256], rss[256];
    rs[tid] = s; rss[tid] = ss;
    __syncthreads();
    for (int o = 128; o > 0; o >>= 1) {
        if (tid < o) { rs[tid] += rs[tid + o]; rss[tid] += rss[tid + o]; }
        __syncthreads();
    }
    float mean = rs[0] * (1.f / 16384.f);
    float var  = rss[0] * (1.f / 16384.f) - mean * mean;
    float inv  = rsqrtf(var + 1e-5f);

    for (int e = tid; e < 16 * 1024; e += 256) {
        int cl = e >> 10;
        float v = (xp[e] - mean) * inv;
        op[e] = v * gamma[g * 16 + cl] + beta[g * 16 + cl];
    }
}

// ---------------- TF32 tensor-core GEMM -------------------------------------
// C[b] = W (M x K) @ B[b] (K x 1024) + bias (+resid)
// Block tile 128x128, BK=32, 256 threads (8 warps, 2x4), warp tile 64x32.
__device__ __forceinline__ uint32_t f2tf(float x) {
    uint32_t r;
    asm("cvt.rna.tf32.f32 %0, %1;" : "=r"(r) : "f"(x));
    return r;
}

__global__ __launch_bounds__(256, 2)
void gemm_tf32_kernel(const float* __restrict__ W,
                      const float* __restrict__ Bmat,
                      const float* __restrict__ bias,
                      const float* __restrict__ resid,
                      float* __restrict__ Cout,
                      int M, int Kdim) {
    __shared__ uint32_t As[128][36];   // [m][k], pad 4 -> conflict-free frags
    __shared__ uint32_t Bs[32][136];   // [k][n], pad 8 -> conflict-free frags

    int bz = blockIdx.z;
    const float* Bp = Bmat + (size_t)bz * Kdim * 1024;
    float* Cp = Cout + (size_t)bz * M * 1024;
    const float* Rp = resid ? resid + (size_t)bz * M * 1024 : nullptr;

    int m0 = blockIdx.y * 128, n0 = blockIdx.x * 128;
    int tid = threadIdx.x;
    int wid = tid >> 5, lane = tid & 31;
    int warp_m = wid >> 2, warp_n = wid & 3;      // 2 x 4 warps
    int wm0 = warp_m * 64, wn0 = warp_n * 32;
    int gr = lane >> 2, gc = lane & 3;

    // gmem load slots: A 4 float4/thread, B 4 float4/thread
    int a_row[4], a_k4[4], b_row[4], b_n4[4];
#pragma unroll
    for (int i = 0; i < 4; i++) {
        int idx = tid + i * 256;
        a_row[i] = idx >> 3; a_k4[i] = (idx & 7) * 4;    // A: 128 rows x 8 f4
        b_row[i] = idx >> 5; b_n4[i] = (idx & 31) * 4;   // B: 32 rows x 32 f4
    }

    float acc[4][4][4] = {};
    float4 pa[4], pb[4];
    int ktiles = Kdim >> 5;

    // prefetch tile 0
#pragma unroll
    for (int i = 0; i < 4; i++) {
        pa[i] = *(const float4*)&W[(size_t)(m0 + a_row[i]) * Kdim + a_k4[i]];
        pb[i] = *(const float4*)&Bp[(size_t)b_row[i] * 1024 + n0 + b_n4[i]];
    }

    for (int kt = 0; kt < ktiles; kt++) {
        // store prefetched tile to smem with tf32 conversion
#pragma unroll
        for (int i = 0; i < 4; i++) {
            As[a_row[i]][a_k4[i] + 0] = f2tf(pa[i].x);
            As[a_row[i]][a_k4[i] + 1] = f2tf(pa[i].y);
            As[a_row[i]][a_k4[i] + 2] = f2tf(pa[i].z);
            As[a_row[i]][a_k4[i] + 3] = f2tf(pa[i].w);
            Bs[b_row[i]][b_n4[i] + 0] = f2tf(pb[i].x);
            Bs[b_row[i]][b_n4[i] + 1] = f2tf(pb[i].y);
            Bs[b_row[i]][b_n4[i] + 2] = f2tf(pb[i].z);
            Bs[b_row[i]][b_n4[i] + 3] = f2tf(pb[i].w);
        }
        __syncthreads();

        // prefetch next tile (overlaps with compute below)
        if (kt + 1 < ktiles) {
            int k0 = (kt + 1) * 32;
#pragma unroll
            for (int i = 0; i < 4; i++) {
                pa[i] = *(const float4*)&W[(size_t)(m0 + a_row[i]) * Kdim + k0 + a_k4[i]];
                pb[i] = *(const float4*)&Bp[(size_t)(k0 + b_row[i]) * 1024 + n0 + b_n4[i]];
            }
        }

#pragma unroll
        for (int kk = 0; kk < 32; kk += 8) {
            uint32_t af[4][4], bf[4][2];
#pragma unroll
            for (int mt = 0; mt < 4; mt++) {
                int r = wm0 + mt * 16 + gr;
                af[mt][0] = As[r][kk + gc];
                af[mt][1] = As[r + 8][kk + gc];
                af[mt][2] = As[r][kk + gc + 4];
                af[mt][3] = As[r + 8][kk + gc + 4];
            }
#pragma unroll
            for (int nt = 0; nt < 4; nt++) {
                int n = wn0 + nt * 8 + gr;
                bf[nt][0] = Bs[kk + gc][n];
                bf[nt][1] = Bs[kk + gc + 4][n];
            }
#pragma unroll
            for (int mt = 0; mt < 4; mt++)
#pragma unroll
                for (int nt = 0; nt < 4; nt++) {
                    float* c = acc[mt][nt];
                    asm volatile(
                        "mma.sync.aligned.m16n8k8.row.col.f32.tf32.tf32.f32 "
                        "{%0,%1,%2,%3}, {%4,%5,%6,%7}, {%8,%9}, {%0,%1,%2,%3};"
                        : "+f"(c[0]), "+f"(c[1]), "+f"(c[2]), "+f"(c[3])
                        : "r"(af[mt][0]), "r"(af[mt][1]), "r"(af[mt][2]), "r"(af[mt][3]),
                          "r"(bf[nt][0]), "r"(bf[nt][1]));
                }
        }
        __syncthreads();
    }

    // epilogue: bias (+resid), write float2 pairs
#pragma unroll
    for (int mt = 0; mt < 4; mt++) {
#pragma unroll
        for (int nt = 0; nt < 4; nt++) {
            int r0 = m0 + wm0 + mt * 16 + gr;
            int cc = n0 + wn0 + nt * 8 + gc * 2;
            float bv0 = bias[r0], bv1 = bias[r0 + 8];
            float* c = acc[mt][nt];
            float2 o0 = make_float2(c[0] + bv0, c[1] + bv0);
            float2 o1 = make_float2(c[2] + bv1, c[3] + bv1);
            size_t off0 = (size_t)r0 * 1024 + cc;
            size_t off1 = (size_t)(r0 + 8) * 1024 + cc;
            if (Rp) {
                float2 r0v = *(const float2*)&Rp[off0];
                float2 r1v = *(const float2*)&Rp[off1];
                o0.x += r0v.x; o0.y += r0v.y;
                o1.x += r1v.x; o1.y += r1v.y;
            }
            *(float2*)&Cp[off0] = o0;
            *(float2*)&Cp[off1] = o1;
        }
    }
}

// ---------------- Attention (flash-style, 64 t-rows per block) --------------
extern __shared__ float attn_smem[];
__global__ void attn_kernel(const float* __restrict__ qkv,
                            float* __restrict__ aout) {
    float* Qs = attn_smem;            // [64][64]  Q (scaled), [c][t]
    float* KP = Qs + 64 * 64;         // [64][68]  K ([c][s]) then P ([t][s])
    float* Vt = KP + 64 * 68;         // [64][68]  V transposed [s][c]

    int bh = blockIdx.y;
    int b = bh >> 3, h = bh & 7;
    const float* base = qkv + ((size_t)b * 1536 + h * 192) * 1024;
    const float* Qp = base;
    const float* Kp = base + 64 * 1024;
    const float* Vp = base + 128 * 1024;
    int t0 = blockIdx.x * 64;

    int tid = threadIdx.x;
    int ty = tid >> 4, tx = tid & 15;

    for (int it = 0; it < 4; it++) {
        int idx = tid + it * 256;
        int c = idx >> 4;
        int t4 = (idx & 15) * 4;
        float4 v = *(const float4*)&Qp[(size_t)c * 1024 + t0 + t4];
        v.x *= 0.125f; v.y *= 0.125f; v.z *= 0.125f; v.w *= 0.125f;
        *(float4*)&Qs[c * 64 + t4] = v;
    }

    float O[4][4] = {};
    float mrow[4] = {-INFINITY, -INFINITY, -INFINITY, -INFINITY};
    float lrow[4] = {};

    for (int s0 = 0; s0 < 1024; s0 += 64) {
        __syncthreads();

        for (int it = 0; it < 4; it++) {
            int idx = tid + it * 256;
            int c = idx >> 4;
            int s4 = (idx & 15) * 4;
            float4 kv = *(const float4*)&Kp[(size_t)c * 1024 + s0 + s4];
            *(float4*)&KP[c * 68 + s4] = kv;
            float4 vv = *(const float4*)&Vp[(size_t)c * 1024 + s0 + s4];
            Vt[(s4 + 0) * 68 + c] = vv.x;
            Vt[(s4 + 1) * 68 + c] = vv.y;
            Vt[(s4 + 2) * 68 + c] = vv.z;
            Vt[(s4 + 3) * 68 + c] = vv.w;
        }
        __syncthreads();

        float S[4][4] = {};
#pragma unroll 8
        for (int c = 0; c < 64; c++) {
            float4 q4 = *(const float4*)&Qs[c * 64 + ty * 4];
            float4 k4 = *(const float4*)&KP[c * 68 + tx * 4];
            float qv[4] = {q4.x, q4.y, q4.z, q4.w};
            float kv[4] = {k4.x, k4.y, k4.z, k4.w};
#pragma unroll
            for (int i = 0; i < 4; i++)
#pragma unroll
                for (int j = 0; j < 4; j++)
                    S[i][j] = fmaf(qv[i], kv[j], S[i][j]);
        }

#pragma unroll
        for (int i = 0; i < 4; i++) {
            float mx = fmaxf(fmaxf(S[i][0], S[i][1]), fmaxf(S[i][2], S[i][3]));
#pragma unroll
            for (int off = 8; off > 0; off >>= 1)
                mx = fmaxf(mx, __shfl_xor_sync(0xffffffffu, mx, off));
            float mnew = fmaxf(mrow[i], mx);
            float corr = __expf(mrow[i] - mnew);
            float rsum = 0.f;
#pragma unroll
            for (int j = 0; j < 4; j++) {
                float p = __expf(S[i][j] - mnew);
                S[i][j] = p;
                rsum += p;
            }
#pragma unroll
            for (int off = 8; off > 0; off >>= 1)
                rsum += __shfl_xor_sync(0xffffffffu, rsum, off);
            lrow[i] = lrow[i] * corr + rsum;
            mrow[i] = mnew;
#pragma unroll
            for (int j = 0; j < 4; j++) O[i][j] *= corr;
        }

        __syncthreads();

#pragma unroll
        for (int i = 0; i < 4; i++)
            *(float4*)&KP[(ty * 4 + i) * 68 + tx * 4] =
                make_float4(S[i][0], S[i][1], S[i][2], S[i][3]);
        __syncthreads();

#pragma unroll 8
        for (int s = 0; s < 64; s++) {
            float4 v4 = *(const float4*)&Vt[s * 68 + tx * 4];
            float vv[4] = {v4.x, v4.y, v4.z, v4.w};
#pragma unroll
            for (int i = 0; i < 4; i++) {
                float p = KP[(ty * 4 + i) * 68 + s];
#pragma unroll
                for (int j = 0; j < 4; j++)
                    O[i][j] = fmaf(p, vv[j], O[i][j]);
            }
        }
    }

    __syncthreads();
#pragma unroll
    for (int i = 0; i < 4; i++) {
        float invl = 1.f / lrow[i];
#pragma unroll
        for (int j = 0; j < 4; j++)
            Vt[(tx * 4 + j) * 68 + ty * 4 + i] = O[i][j] * invl;
    }
    __syncthreads();
    float* ap = aout + ((size_t)b * 512 + h * 64) * 1024;
    for (int it = 0; it < 4; it++) {
        int idx = tid + it * 256;
        int c = idx >> 4;
        int t4 = (idx & 15) * 4;
        *(float4*)&ap[(size_t)c * 1024 + t0 + t4] =
            *(const float4*)&Vt[c * 68 + t4];
    }
}

// ---------------- launch ----------------------------------------------------
extern "C" void kernel_launch(void* const* d_in, const int* in_sizes, int n_in,
                              void* d_out, int out_size) {
    const float* x      = (const float*)d_in[0];
    const float* gamma  = (const float*)d_in[1];
    const float* beta   = (const float*)d_in[2];
    const float* w_qkv  = (const float*)d_in[3];
    const float* b_qkv  = (const float*)d_in[4];
    const float* w_proj = (const float*)d_in[5];
    const float* b_proj = (const float*)d_in[6];
    float* out = (float*)d_out;

    float *h_ptr, *qkv_ptr, *a_ptr;
    cudaGetSymbolAddress((void**)&h_ptr, g_h);
    cudaGetSymbolAddress((void**)&qkv_ptr, g_qkv);
    cudaGetSymbolAddress((void**)&a_ptr, g_a);

    // 1) GroupNorm
    groupnorm_kernel<<<8 * 32, 256>>>(x, gamma, beta, h_ptr);

    // 2) QKV GEMM: [1536,512] @ [512,1024] per batch (tf32 tensor cores)
    gemm_tf32_kernel<<<dim3(8, 12, 8), 256>>>(w_qkv, h_ptr, b_qkv, nullptr,
                                              qkv_ptr, 1536, 512);

    // 3) Attention
    cudaFuncSetAttribute(attn_kernel,
                         cudaFuncAttributeMaxDynamicSharedMemorySize, 51200);
    attn_kernel<<<dim3(16, 64), 256, 51200>>>(qkv_ptr, a_ptr);

    // 4) Proj GEMM + bias + residual (tf32 tensor cores)
    gemm_tf32_kernel<<<dim3(8, 4, 8), 256>>>(w_proj, a_ptr, b_proj, x,
                                             out, 512, 512);
}

// round 5
// speedup vs baseline: 2.6960x; 1.8336x over previous
#include <cuda_runtime.h>
#include <math.h>
#include <stdint.h>

// ---------------- scratch (static device globals; no allocation) ------------
__device__ float g_h[8 * 512 * 1024];      // groupnorm output   [b,c,t]
__device__ float g_qkv[8 * 1536 * 1024];   // qkv projection     [b,3c,t] (only V rows valid)
__device__ float g_a[8 * 512 * 1024];      // attention output   [b,c,t]
__device__ float g_qT[64 * 1024 * 64];     // Q transposed [bh][t][c]
__device__ float g_kT[64 * 1024 * 64];     // K transposed [bh][s][c]

__device__ __forceinline__ uint32_t f2tf(float x) {
    uint32_t r;
    asm("cvt.rna.tf32.f32 %0, %1;" : "=r"(r) : "f"(x));
    return r;
}

// ---------------- GroupNorm -------------------------------------------------
__global__ void groupnorm_kernel(const float* __restrict__ x,
                                 const float* __restrict__ gamma,
                                 const float* __restrict__ beta,
                                 float* __restrict__ out) {
    int b = blockIdx.x >> 5;
    int g = blockIdx.x & 31;
    const float* xp = x + ((size_t)b * 512 + g * 16) * 1024;
    float* op = out + ((size_t)b * 512 + g * 16) * 1024;
    int tid = threadIdx.x;

    float s = 0.f, ss = 0.f;
    for (int e = tid; e < 16 * 1024; e += 256) {
        float v = xp[e];
        s += v; ss += v * v;
    }
    __shared__ float rs[256], rss[256];
    rs[tid] = s; rss[tid] = ss;
    __syncthreads();
    for (int o = 128; o > 0; o >>= 1) {
        if (tid < o) { rs[tid] += rs[tid + o]; rss[tid] += rss[tid + o]; }
        __syncthreads();
    }
    float mean = rs[0] * (1.f / 16384.f);
    float var  = rss[0] * (1.f / 16384.f) - mean * mean;
    float inv  = rsqrtf(var + 1e-5f);

    for (int e = tid; e < 16 * 1024; e += 256) {
        int cl = e >> 10;
        float v = (xp[e] - mean) * inv;
        op[e] = v * gamma[g * 16 + cl] + beta[g * 16 + cl];
    }
}

// ---------------- TF32 tensor-core GEMM -------------------------------------
// C[b] = W (M x K) @ B[b] (K x 1024) + bias (+resid)
// If qTp != nullptr (qkv mode): q/k rows are routed to transposed buffers
// [bh][t][c] instead of the normal [o][t] output; v rows go to Cout.
__global__ __launch_bounds__(256, 2)
void gemm_tf32_kernel(const float* __restrict__ W,
                      const float* __restrict__ Bmat,
                      const float* __restrict__ bias,
                      const float* __restrict__ resid,
                      float* __restrict__ Cout,
                      float* __restrict__ qTp,
                      float* __restrict__ kTp,
                      int M, int Kdim) {
    __shared__ uint32_t As[128][36];
    __shared__ uint32_t Bs[32][136];

    int bz = blockIdx.z;
    const float* Bp = Bmat + (size_t)bz * Kdim * 1024;
    float* Cp = Cout + (size_t)bz * M * 1024;
    const float* Rp = resid ? resid + (size_t)bz * M * 1024 : nullptr;

    int m0 = blockIdx.y * 128, n0 = blockIdx.x * 128;
    int tid = threadIdx.x;
    int wid = tid >> 5, lane = tid & 31;
    int warp_m = wid >> 2, warp_n = wid & 3;
    int wm0 = warp_m * 64, wn0 = warp_n * 32;
    int gr = lane >> 2, gc = lane & 3;

    int a_row[4], a_k4[4], b_row[4], b_n4[4];
#pragma unroll
    for (int i = 0; i < 4; i++) {
        int idx = tid + i * 256;
        a_row[i] = idx >> 3; a_k4[i] = (idx & 7) * 4;
        b_row[i] = idx >> 5; b_n4[i] = (idx & 31) * 4;
    }

    float acc[4][4][4] = {};
    float4 pa[4], pb[4];
    int ktiles = Kdim >> 5;

#pragma unroll
    for (int i = 0; i < 4; i++) {
        pa[i] = *(const float4*)&W[(size_t)(m0 + a_row[i]) * Kdim + a_k4[i]];
        pb[i] = *(const float4*)&Bp[(size_t)b_row[i] * 1024 + n0 + b_n4[i]];
    }

    for (int kt = 0; kt < ktiles; kt++) {
#pragma unroll
        for (int i = 0; i < 4; i++) {
            As[a_row[i]][a_k4[i] + 0] = f2tf(pa[i].x);
            As[a_row[i]][a_k4[i] + 1] = f2tf(pa[i].y);
            As[a_row[i]][a_k4[i] + 2] = f2tf(pa[i].z);
            As[a_row[i]][a_k4[i] + 3] = f2tf(pa[i].w);
            Bs[b_row[i]][b_n4[i] + 0] = f2tf(pb[i].x);
            Bs[b_row[i]][b_n4[i] + 1] = f2tf(pb[i].y);
            Bs[b_row[i]][b_n4[i] + 2] = f2tf(pb[i].z);
            Bs[b_row[i]][b_n4[i] + 3] = f2tf(pb[i].w);
        }
        __syncthreads();

        if (kt + 1 < ktiles) {
            int k0 = (kt + 1) * 32;
#pragma unroll
            for (int i = 0; i < 4; i++) {
                pa[i] = *(const float4*)&W[(size_t)(m0 + a_row[i]) * Kdim + k0 + a_k4[i]];
                pb[i] = *(const float4*)&Bp[(size_t)(k0 + b_row[i]) * 1024 + n0 + b_n4[i]];
            }
        }

#pragma unroll
        for (int kk = 0; kk < 32; kk += 8) {
            uint32_t af[4][4], bf[4][2];
#pragma unroll
            for (int mt = 0; mt < 4; mt++) {
                int r = wm0 + mt * 16 + gr;
                af[mt][0] = As[r][kk + gc];
                af[mt][1] = As[r + 8][kk + gc];
                af[mt][2] = As[r][kk + gc + 4];
                af[mt][3] = As[r + 8][kk + gc + 4];
            }
#pragma unroll
            for (int nt = 0; nt < 4; nt++) {
                int n = wn0 + nt * 8 + gr;
                bf[nt][0] = Bs[kk + gc][n];
                bf[nt][1] = Bs[kk + gc + 4][n];
            }
#pragma unroll
            for (int mt = 0; mt < 4; mt++)
#pragma unroll
                for (int nt = 0; nt < 4; nt++) {
                    float* c = acc[mt][nt];
                    asm volatile(
                        "mma.sync.aligned.m16n8k8.row.col.f32.tf32.tf32.f32 "
                        "{%0,%1,%2,%3}, {%4,%5,%6,%7}, {%8,%9}, {%0,%1,%2,%3};"
                        : "+f"(c[0]), "+f"(c[1]), "+f"(c[2]), "+f"(c[3])
                        : "r"(af[mt][0]), "r"(af[mt][1]), "r"(af[mt][2]), "r"(af[mt][3]),
                          "r"(bf[nt][0]), "r"(bf[nt][1]));
                }
        }
        __syncthreads();
    }

    bool route = (qTp != nullptr);
#pragma unroll
    for (int mt = 0; mt < 4; mt++) {
#pragma unroll
        for (int nt = 0; nt < 4; nt++) {
            int r0 = m0 + wm0 + mt * 16 + gr;
            int cc = n0 + wn0 + nt * 8 + gc * 2;
            float bv0 = bias[r0], bv1 = bias[r0 + 8];
            float* c = acc[mt][nt];
            if (!route) {
                size_t off0 = (size_t)r0 * 1024 + cc;
                size_t off1 = (size_t)(r0 + 8) * 1024 + cc;
                float2 o0 = make_float2(c[0] + bv0, c[1] + bv0);
                float2 o1 = make_float2(c[2] + bv1, c[3] + bv1);
                if (Rp) {
                    float2 r0v = *(const float2*)&Rp[off0];
                    float2 r1v = *(const float2*)&Rp[off1];
                    o0.x += r0v.x; o0.y += r0v.y;
                    o1.x += r1v.x; o1.y += r1v.y;
                }
                *(float2*)&Cp[off0] = o0;
                *(float2*)&Cp[off1] = o1;
            } else {
#pragma unroll
                for (int e = 0; e < 4; e++) {
                    int m = r0 + ((e >> 1) << 3);
                    int n = cc + (e & 1);
                    float val = c[e] + ((e >> 1) ? bv1 : bv0);
                    int head = m / 192;
                    int r = m - head * 192;
                    size_t bh = (size_t)(bz * 8 + head);
                    if (r < 64)
                        qTp[(bh * 1024 + n) * 64 + r] = val;
                    else if (r < 128)
                        kTp[(bh * 1024 + n) * 64 + (r - 64)] = val;
                    else
                        Cp[(size_t)m * 1024 + n] = val;
                }
            }
        }
    }
}

// ---------------- TF32 tensor-core flash attention --------------------------
// Per block: 64 t-rows of one (b,h). 256 threads = 8 warps (4 m x 2 n).
// S = Q^T K via mma (A = qT [t][c], B = kT [s][c]); softmax in smem;
// O += P V via mma (A = P [t][s], B = V [c][s]).
#define AST 68
extern __shared__ float attn_smem[];
__global__ __launch_bounds__(256, 2)
void attn_tf32_kernel(const float* __restrict__ qT,
                      const float* __restrict__ kT,
                      const float* __restrict__ qkv,
                      float* __restrict__ aout) {
    uint32_t* Qt = (uint32_t*)attn_smem;               // [64][AST] t x c (tf32)
    uint32_t* Kt = (uint32_t*)(attn_smem + 64 * AST);  // [64][AST] s x c (tf32)
    uint32_t* Vs = (uint32_t*)(attn_smem + 2 * 64 * AST); // [64][AST] c x s (tf32)
    float* Ss = attn_smem + 3 * 64 * AST;              // [64][AST] t x s
    float* m_s = attn_smem + 4 * 64 * AST;
    float* l_s = m_s + 64;
    float* corr_s = l_s + 64;

    int bh = blockIdx.y;
    int b = bh >> 3, h = bh & 7;
    int t0 = blockIdx.x * 64;
    const float* Qp = qT + (size_t)bh * 1024 * 64;
    const float* Kp = kT + (size_t)bh * 1024 * 64;
    const float* Vp = qkv + ((size_t)b * 1536 + h * 192 + 128) * 1024;

    int tid = threadIdx.x;
    int wid = tid >> 5, lane = tid & 31;
    int warp_m = wid >> 1, warp_n = wid & 1;
    int wm0 = warp_m * 16;     // 16 t-rows per warp
    int wn0 = warp_n * 32;     // 32 cols per warp (s for S, c for O)
    int gr = lane >> 2, gc = lane & 3;

    // Q tile: [t][c], scaled 0.125, tf32
    for (int it = 0; it < 4; it++) {
        int idx = tid + it * 256;
        int t = idx >> 4;
        int c4 = (idx & 15) * 4;
        float4 v = *(const float4*)&Qp[(size_t)(t0 + t) * 64 + c4];
        Qt[t * AST + c4 + 0] = f2tf(v.x * 0.125f);
        Qt[t * AST + c4 + 1] = f2tf(v.y * 0.125f);
        Qt[t * AST + c4 + 2] = f2tf(v.z * 0.125f);
        Qt[t * AST + c4 + 3] = f2tf(v.w * 0.125f);
    }
    if (tid < 64) { m_s[tid] = -INFINITY; l_s[tid] = 0.f; }

    float O[4][4] = {};

    for (int s0 = 0; s0 < 1024; s0 += 64) {
        __syncthreads();   // prev-iter smem reads done; init visible

        // K tile [s][c] and V tile [c][s]
        for (int it = 0; it < 4; it++) {
            int idx = tid + it * 256;
            int r = idx >> 4;
            int c4 = (idx & 15) * 4;
            float4 kv = *(const float4*)&Kp[(size_t)(s0 + r) * 64 + c4];
            Kt[r * AST + c4 + 0] = f2tf(kv.x);
            Kt[r * AST + c4 + 1] = f2tf(kv.y);
            Kt[r * AST + c4 + 2] = f2tf(kv.z);
            Kt[r * AST + c4 + 3] = f2tf(kv.w);
            float4 vv = *(const float4*)&Vp[(size_t)r * 1024 + s0 + c4];
            Vs[r * AST + c4 + 0] = f2tf(vv.x);
            Vs[r * AST + c4 + 1] = f2tf(vv.y);
            Vs[r * AST + c4 + 2] = f2tf(vv.z);
            Vs[r * AST + c4 + 3] = f2tf(vv.w);
        }
        __syncthreads();

        // S = Q^T K (warp: 16 rows x 32 cols)
        float Sa[4][4] = {};
#pragma unroll
        for (int kk = 0; kk < 64; kk += 8) {
            uint32_t a0 = Qt[(wm0 + gr) * AST + kk + gc];
            uint32_t a1 = Qt[(wm0 + gr + 8) * AST + kk + gc];
            uint32_t a2 = Qt[(wm0 + gr) * AST + kk + gc + 4];
            uint32_t a3 = Qt[(wm0 + gr + 8) * AST + kk + gc + 4];
#pragma unroll
            for (int nt = 0; nt < 4; nt++) {
                int n = wn0 + nt * 8 + gr;
                uint32_t b0 = Kt[n * AST + kk + gc];
                uint32_t b1 = Kt[n * AST + kk + gc + 4];
                float* c = Sa[nt];
                asm volatile(
                    "mma.sync.aligned.m16n8k8.row.col.f32.tf32.tf32.f32 "
                    "{%0,%1,%2,%3}, {%4,%5,%6,%7}, {%8,%9}, {%0,%1,%2,%3};"
                    : "+f"(c[0]), "+f"(c[1]), "+f"(c[2]), "+f"(c[3])
                    : "r"(a0), "r"(a1), "r"(a2), "r"(a3), "r"(b0), "r"(b1));
            }
        }
        // S frags -> smem
#pragma unroll
        for (int nt = 0; nt < 4; nt++) {
            int cc = wn0 + nt * 8 + gc * 2;
            Ss[(wm0 + gr) * AST + cc]     = Sa[nt][0];
            Ss[(wm0 + gr) * AST + cc + 1] = Sa[nt][1];
            Ss[(wm0 + gr + 8) * AST + cc]     = Sa[nt][2];
            Ss[(wm0 + gr + 8) * AST + cc + 1] = Sa[nt][3];
        }
        __syncthreads();

        // softmax: 4 threads per row, 16 cols each
        {
            int row = tid >> 2;
            int q = tid & 3;
            float* rp = &Ss[row * AST + q * 16];
            float e[16];
            float mx = -INFINITY;
#pragma unroll
            for (int u4 = 0; u4 < 4; u4++) {
                float4 v = *(const float4*)&rp[u4 * 4];
                e[u4 * 4 + 0] = v.x; e[u4 * 4 + 1] = v.y;
                e[u4 * 4 + 2] = v.z; e[u4 * 4 + 3] = v.w;
                mx = fmaxf(mx, fmaxf(fmaxf(v.x, v.y), fmaxf(v.z, v.w)));
            }
            mx = fmaxf(mx, __shfl_xor_sync(0xffffffffu, mx, 1));
            mx = fmaxf(mx, __shfl_xor_sync(0xffffffffu, mx, 2));
            float mold = m_s[row];
            float mnew = fmaxf(mold, mx);
            float rsum = 0.f;
#pragma unroll
            for (int u = 0; u < 16; u++) {
                float p = __expf(e[u] - mnew);
                rsum += p;
                rp[u] = __uint_as_float(f2tf(p));
            }
            rsum += __shfl_xor_sync(0xffffffffu, rsum, 1);
            rsum += __shfl_xor_sync(0xffffffffu, rsum, 2);
            if (q == 0) {
                float corr = __expf(mold - mnew);
                l_s[row] = l_s[row] * corr + rsum;
                m_s[row] = mnew;
                corr_s[row] = corr;
            }
        }
        __syncthreads();

        // rescale O, then O += P V
        float cr0 = corr_s[wm0 + gr];
        float cr1 = corr_s[wm0 + gr + 8];
#pragma unroll
        for (int nt = 0; nt < 4; nt++) {
            O[nt][0] *= cr0; O[nt][1] *= cr0;
            O[nt][2] *= cr1; O[nt][3] *= cr1;
        }
#pragma unroll
        for (int kk = 0; kk < 64; kk += 8) {
            uint32_t a0 = __float_as_uint(Ss[(wm0 + gr) * AST + kk + gc]);
            uint32_t a1 = __float_as_uint(Ss[(wm0 + gr + 8) * AST + kk + gc]);
            uint32_t a2 = __float_as_uint(Ss[(wm0 + gr) * AST + kk + gc + 4]);
            uint32_t a3 = __float_as_uint(Ss[(wm0 + gr + 8) * AST + kk + gc + 4]);
#pragma unroll
            for (int nt = 0; nt < 4; nt++) {
                int n = wn0 + nt * 8 + gr;
                uint32_t b0 = Vs[n * AST + kk + gc];
                uint32_t b1 = Vs[n * AST + kk + gc + 4];
                float* c = O[nt];
                asm volatile(
                    "mma.sync.aligned.m16n8k8.row.col.f32.tf32.tf32.f32 "
                    "{%0,%1,%2,%3}, {%4,%5,%6,%7}, {%8,%9}, {%0,%1,%2,%3};"
                    : "+f"(c[0]), "+f"(c[1]), "+f"(c[2]), "+f"(c[3])
                    : "r"(a0), "r"(a1), "r"(a2), "r"(a3), "r"(b0), "r"(b1));
            }
        }
    }
    __syncthreads();   // last PV reads of Ss done

    // normalize + transpose O ([t][c] -> [c][t]) via Ss
    {
        float inv0 = 1.f / l_s[wm0 + gr];
        float inv1 = 1.f / l_s[wm0 + gr + 8];
#pragma unroll
        for (int nt = 0; nt < 4; nt++) {
            int cc = wn0 + nt * 8 + gc * 2;
            Ss[cc * AST + wm0 + gr]           = O[nt][0] * inv0;
            Ss[(cc + 1) * AST + wm0 + gr]     = O[nt][1] * inv0;
            Ss[cc * AST + wm0 + gr + 8]       = O[nt][2] * inv1;
            Ss[(cc + 1) * AST + wm0 + gr + 8] = O[nt][3] * inv1;
        }
    }
    __syncthreads();
    float* ap = aout + ((size_t)b * 512 + h * 64) * 1024;
    for (int it = 0; it < 4; it++) {
        int idx = tid + it * 256;
        int c = idx >> 4;
        int t4 = (idx & 15) * 4;
        *(float4*)&ap[(size_t)c * 1024 + t0 + t4] =
            *(const float4*)&Ss[c * AST + t4];
    }
}

// ---------------- launch ----------------------------------------------------
extern "C" void kernel_launch(void* const* d_in, const int* in_sizes, int n_in,
                              void* d_out, int out_size) {
    const float* x      = (const float*)d_in[0];
    const float* gamma  = (const float*)d_in[1];
    const float* beta   = (const float*)d_in[2];
    const float* w_qkv  = (const float*)d_in[3];
    const float* b_qkv  = (const float*)d_in[4];
    const float* w_proj = (const float*)d_in[5];
    const float* b_proj = (const float*)d_in[6];
    float* out = (float*)d_out;

    float *h_ptr, *qkv_ptr, *a_ptr, *qT_ptr, *kT_ptr;
    cudaGetSymbolAddress((void**)&h_ptr, g_h);
    cudaGetSymbolAddress((void**)&qkv_ptr, g_qkv);
    cudaGetSymbolAddress((void**)&a_ptr, g_a);
    cudaGetSymbolAddress((void**)&qT_ptr, g_qT);
    cudaGetSymbolAddress((void**)&kT_ptr, g_kT);

    // 1) GroupNorm
    groupnorm_kernel<<<8 * 32, 256>>>(x, gamma, beta, h_ptr);

    // 2) QKV GEMM (tf32): q/k routed to transposed buffers, v -> qkv buffer
    gemm_tf32_kernel<<<dim3(8, 12, 8), 256>>>(w_qkv, h_ptr, b_qkv, nullptr,
                                              qkv_ptr, qT_ptr, kT_ptr,
                                              1536, 512);

    // 3) Attention (tf32 tensor cores)
    cudaFuncSetAttribute(attn_tf32_kernel,
                         cudaFuncAttributeMaxDynamicSharedMemorySize, 70400);
    attn_tf32_kernel<<<dim3(16, 64), 256, 70400>>>(qT_ptr, kT_ptr, qkv_ptr,
                                                   a_ptr);

    // 4) Proj GEMM + bias + residual (tf32)
    gemm_tf32_kernel<<<dim3(8, 4, 8), 256>>>(w_proj, a_ptr, b_proj, x,
                                             out, nullptr, nullptr, 512, 512);
}

// round 7
// speedup vs baseline: 3.8674x; 1.4345x over previous
#include <cuda_runtime.h>
#include <cuda_bf16.h>
#include <math.h>
#include <stdint.h>

// ---------------- scratch (static device globals; no allocation) ------------
__device__ float g_hT[8 * 1024 * 512];     // groupnorm output transposed [b][t][c]
__device__ float g_qkv[8 * 1536 * 1024];   // qkv projection [b,3c,t] (only V rows used)
__device__ float g_aT[8 * 1024 * 512];     // attention output transposed [b][t][c]
__device__ float g_qT[64 * 1024 * 64];     // Q [bh][t][c]
__device__ float g_kT[64 * 1024 * 64];     // K [bh][s][c]

__device__ __forceinline__ uint32_t pack_bf16(float lo, float hi) {
    uint32_t r;
    asm("cvt.rn.bf16x2.f32 %0, %1, %2;" : "=r"(r) : "f"(hi), "f"(lo));
    return r;
}

#define MMA_BF16(c, a0, a1, a2, a3, b0, b1)                                   \
    asm volatile(                                                             \
        "mma.sync.aligned.m16n8k16.row.col.f32.bf16.bf16.f32 "                \
        "{%0,%1,%2,%3}, {%4,%5,%6,%7}, {%8,%9}, {%0,%1,%2,%3};"               \
        : "+f"((c)[0]), "+f"((c)[1]), "+f"((c)[2]), "+f"((c)[3])              \
        : "r"(a0), "r"(a1), "r"(a2), "r"(a3), "r"(b0), "r"(b1))

// ---------------- GroupNorm (writes transposed hT [b][t][c]) ----------------
__global__ void groupnorm_t_kernel(const float* __restrict__ x,
                                   const float* __restrict__ gamma,
                                   const float* __restrict__ beta,
                                   float* __restrict__ hT) {
    int b = blockIdx.x >> 5;
    int g = blockIdx.x & 31;
    const float* xp = x + ((size_t)b * 512 + g * 16) * 1024;
    int tid = threadIdx.x;

    float s = 0.f, ss = 0.f;
    for (int e = tid; e < 16 * 1024; e += 256) {
        float v = xp[e];
        s += v; ss += v * v;
    }
    __shared__ float rs[256], rss[256];
    __shared__ float Ts[64][20];
    rs[tid] = s; rss[tid] = ss;
    __syncthreads();
    for (int o = 128; o > 0; o >>= 1) {
        if (tid < o) { rs[tid] += rs[tid + o]; rss[tid] += rss[tid + o]; }
        __syncthreads();
    }
    float mean = rs[0] * (1.f / 16384.f);
    float var  = rss[0] * (1.f / 16384.f) - mean * mean;
    float inv  = rsqrtf(var + 1e-5f);

    int cl = tid >> 4;             // 0..15 channel within group (load phase)
    int tw4 = (tid & 15) * 4;      // 0..60 t within tile
    float scale = inv * gamma[g * 16 + cl];
    float shift = beta[g * 16 + cl] - mean * scale;
    float* hTb = hT + (size_t)b * 1024 * 512 + g * 16;
    int tr = tid >> 2, q = tid & 3;   // write phase mapping

    for (int t0 = 0; t0 < 1024; t0 += 64) {
        float4 v = *(const float4*)&xp[cl * 1024 + t0 + tw4];
        Ts[tw4 + 0][cl] = v.x * scale + shift;
        Ts[tw4 + 1][cl] = v.y * scale + shift;
        Ts[tw4 + 2][cl] = v.z * scale + shift;
        Ts[tw4 + 3][cl] = v.w * scale + shift;
        __syncthreads();
        *(float4*)&hTb[(size_t)(t0 + tr) * 512 + q * 4] =
            *(const float4*)&Ts[tr][q * 4];
        __syncthreads();
    }
}

// ---------------- BF16 tensor-core GEMM -------------------------------------
// C[b](M x 1024) = W (M x K) @ BT[b]^T  where BT is [1024][K] (n-major, k contig)
// 128x128 block tile, BK=32, 256 threads (8 warps 2x4), warp tile 64x32.
__global__ __launch_bounds__(256, 2)
void gemm_bf16_kernel(const float* __restrict__ W,
                      const float* __restrict__ BT,
                      const float* __restrict__ bias,
                      const float* __restrict__ resid,
                      float* __restrict__ Cout,
                      float* __restrict__ qTp,
                      float* __restrict__ kTp,
                      int M, int Kdim) {
    __shared__ __nv_bfloat16 As[128][40];   // [m][k]
    __shared__ __nv_bfloat16 Bs[128][40];   // [n][k]

    int bz = blockIdx.z;
    const float* Bp = BT + (size_t)bz * 1024 * Kdim;
    float* Cp = Cout + (size_t)bz * M * 1024;
    const float* Rp = resid ? resid + (size_t)bz * M * 1024 : nullptr;

    int m0 = blockIdx.y * 128, n0 = blockIdx.x * 128;
    int tid = threadIdx.x;
    int wid = tid >> 5, lane = tid & 31;
    int warp_m = wid >> 2, warp_n = wid & 3;
    int wm0 = warp_m * 64, wn0 = warp_n * 32;
    int gr = lane >> 2, gc = lane & 3;

    // both tiles: 128 rows x 32 k = 8 float4 per row
    int rr[4], k4[4];
#pragma unroll
    for (int i = 0; i < 4; i++) {
        int idx = tid + i * 256;
        rr[i] = idx >> 3; k4[i] = (idx & 7) * 4;
    }

    float acc[4][4][4] = {};
    float4 pa[4], pb[4];
    int ktiles = Kdim >> 5;

#pragma unroll
    for (int i = 0; i < 4; i++) {
        pa[i] = *(const float4*)&W[(size_t)(m0 + rr[i]) * Kdim + k4[i]];
        pb[i] = *(const float4*)&Bp[(size_t)(n0 + rr[i]) * Kdim + k4[i]];
    }

    for (int kt = 0; kt < ktiles; kt++) {
#pragma unroll
        for (int i = 0; i < 4; i++) {
            *(uint2*)&As[rr[i]][k4[i]] =
                make_uint2(pack_bf16(pa[i].x, pa[i].y), pack_bf16(pa[i].z, pa[i].w));
            *(uint2*)&Bs[rr[i]][k4[i]] =
                make_uint2(pack_bf16(pb[i].x, pb[i].y), pack_bf16(pb[i].z, pb[i].w));
        }
        __syncthreads();

        if (kt + 1 < ktiles) {
            int k0 = (kt + 1) * 32;
#pragma unroll
            for (int i = 0; i < 4; i++) {
                pa[i] = *(const float4*)&W[(size_t)(m0 + rr[i]) * Kdim + k0 + k4[i]];
                pb[i] = *(const float4*)&Bp[(size_t)(n0 + rr[i]) * Kdim + k0 + k4[i]];
            }
        }

#pragma unroll
        for (int kk = 0; kk < 32; kk += 16) {
            uint32_t af[4][4], bf[4][2];
#pragma unroll
            for (int mt = 0; mt < 4; mt++) {
                int r = wm0 + mt * 16 + gr;
                af[mt][0] = *(const uint32_t*)&As[r][kk + gc * 2];
                af[mt][1] = *(const uint32_t*)&As[r + 8][kk + gc * 2];
                af[mt][2] = *(const uint32_t*)&As[r][kk + gc * 2 + 8];
                af[mt][3] = *(const uint32_t*)&As[r + 8][kk + gc * 2 + 8];
            }
#pragma unroll
            for (int nt = 0; nt < 4; nt++) {
                int n = wn0 + nt * 8 + gr;
                bf[nt][0] = *(const uint32_t*)&Bs[n][kk + gc * 2];
                bf[nt][1] = *(const uint32_t*)&Bs[n][kk + gc * 2 + 8];
            }
#pragma unroll
            for (int mt = 0; mt < 4; mt++)
#pragma unroll
                for (int nt = 0; nt < 4; nt++)
                    MMA_BF16(acc[mt][nt], af[mt][0], af[mt][1], af[mt][2],
                             af[mt][3], bf[nt][0], bf[nt][1]);
        }
        __syncthreads();
    }

    bool route = (qTp != nullptr);
#pragma unroll
    for (int mt = 0; mt < 4; mt++) {
#pragma unroll
        for (int nt = 0; nt < 4; nt++) {
            int r0 = m0 + wm0 + mt * 16 + gr;
            int cc = n0 + wn0 + nt * 8 + gc * 2;
            float bv0 = bias[r0], bv1 = bias[r0 + 8];
            float* c = acc[mt][nt];
            if (!route) {
                size_t off0 = (size_t)r0 * 1024 + cc;
                size_t off1 = (size_t)(r0 + 8) * 1024 + cc;
                float2 o0 = make_float2(c[0] + bv0, c[1] + bv0);
                float2 o1 = make_float2(c[2] + bv1, c[3] + bv1);
                if (Rp) {
                    float2 r0v = *(const float2*)&Rp[off0];
                    float2 r1v = *(const float2*)&Rp[off1];
                    o0.x += r0v.x; o0.y += r0v.y;
                    o1.x += r1v.x; o1.y += r1v.y;
                }
                *(float2*)&Cp[off0] = o0;
                *(float2*)&Cp[off1] = o1;
            } else {
#pragma unroll
                for (int e = 0; e < 4; e++) {
                    int m = r0 + ((e >> 1) << 3);
                    int n = cc + (e & 1);
                    float val = c[e] + ((e >> 1) ? bv1 : bv0);
                    int head = m / 192;
                    int r = m - head * 192;
                    size_t bh = (size_t)(bz * 8 + head);
                    if (r < 64)
                        qTp[(bh * 1024 + n) * 64 + r] = val;
                    else if (r < 128)
                        kTp[(bh * 1024 + n) * 64 + (r - 64)] = val;
                    else
                        Cp[(size_t)m * 1024 + n] = val;
                }
            }
        }
    }
}

// ---------------- BF16 tensor-core flash attention --------------------------
// Per block: 64 t-rows of one (b,h). 8 warps (4m x 2n), warp tile 16 x 32.
// S = Q K^T (A = Q[t][c], B = K[s][c]); softmax fp32 in smem -> P bf16;
// O += P V (A = P[t][s], B = V[c][s]). Output written directly to aT [b][t][c].
extern __shared__ char attn_smem[];
__global__ __launch_bounds__(256, 2)
void attn_bf16_kernel(const float* __restrict__ qT,
                      const float* __restrict__ kT,
                      const float* __restrict__ qkv,
                      float* __restrict__ aT) {
    __nv_bfloat16* Qt = (__nv_bfloat16*)attn_smem;   // [64][72] t x c
    __nv_bfloat16* Kt = Qt + 64 * 72;                // [64][72] s x c
    __nv_bfloat16* Vs = Kt + 64 * 72;                // [64][72] c x s
    __nv_bfloat16* Ps = Vs + 64 * 72;                // [64][72] t x s
    float* Ss = (float*)(Ps + 64 * 72);              // [64][68] t x s (fp32)
    float* m_s = Ss + 64 * 68;
    float* l_s = m_s + 64;
    float* corr_s = l_s + 64;

    int bh = blockIdx.y;
    int b = bh >> 3, h = bh & 7;
    int t0 = blockIdx.x * 64;
    const float* Qp = qT + (size_t)bh * 1024 * 64;
    const float* Kp = kT + (size_t)bh * 1024 * 64;
    const float* Vp = qkv + ((size_t)b * 1536 + h * 192 + 128) * 1024;

    int tid = threadIdx.x;
    int wid = tid >> 5, lane = tid & 31;
    int warp_m = wid >> 1, warp_n = wid & 1;
    int wm0 = warp_m * 16;
    int wn0 = warp_n * 32;
    int gr = lane >> 2, gc = lane & 3;

    // Q tile [t][c] scaled by 1/8, bf16
    for (int it = 0; it < 4; it++) {
        int idx = tid + it * 256;
        int t = idx >> 4;
        int c4 = (idx & 15) * 4;
        float4 v = *(const float4*)&Qp[(size_t)(t0 + t) * 64 + c4];
        *(uint2*)&Qt[t * 72 + c4] =
            make_uint2(pack_bf16(v.x * 0.125f, v.y * 0.125f),
                       pack_bf16(v.z * 0.125f, v.w * 0.125f));
    }
    if (tid < 64) { m_s[tid] = -INFINITY; l_s[tid] = 0.f; }

    float O[4][4] = {};

    for (int s0 = 0; s0 < 1024; s0 += 64) {
        __syncthreads();

        // K [s][c], V [c][s]
        for (int it = 0; it < 4; it++) {
            int idx = tid + it * 256;
            int r = idx >> 4;
            int c4 = (idx & 15) * 4;
            float4 kv = *(const float4*)&Kp[(size_t)(s0 + r) * 64 + c4];
            *(uint2*)&Kt[r * 72 + c4] =
                make_uint2(pack_bf16(kv.x, kv.y), pack_bf16(kv.z, kv.w));
            float4 vv = *(const float4*)&Vp[(size_t)r * 1024 + s0 + c4];
            *(uint2*)&Vs[r * 72 + c4] =
                make_uint2(pack_bf16(vv.x, vv.y), pack_bf16(vv.z, vv.w));
        }
        __syncthreads();

        // S = Q K^T  (warp: 16 t x 32 s)
        float Sa[4][4] = {};
#pragma unroll
        for (int kk = 0; kk < 64; kk += 16) {
            uint32_t a0 = *(const uint32_t*)&Qt[(wm0 + gr) * 72 + kk + gc * 2];
            uint32_t a1 = *(const uint32_t*)&Qt[(wm0 + gr + 8) * 72 + kk + gc * 2];
            uint32_t a2 = *(const uint32_t*)&Qt[(wm0 + gr) * 72 + kk + gc * 2 + 8];
            uint32_t a3 = *(const uint32_t*)&Qt[(wm0 + gr + 8) * 72 + kk + gc * 2 + 8];
#pragma unroll
            for (int nt = 0; nt < 4; nt++) {
                int n = wn0 + nt * 8 + gr;
                uint32_t b0 = *(const uint32_t*)&Kt[n * 72 + kk + gc * 2];
                uint32_t b1 = *(const uint32_t*)&Kt[n * 72 + kk + gc * 2 + 8];
                MMA_BF16(Sa[nt], a0, a1, a2, a3, b0, b1);
            }
        }
#pragma unroll
        for (int nt = 0; nt < 4; nt++) {
            int cc = wn0 + nt * 8 + gc * 2;
            Ss[(wm0 + gr) * 68 + cc]     = Sa[nt][0];
            Ss[(wm0 + gr) * 68 + cc + 1] = Sa[nt][1];
            Ss[(wm0 + gr + 8) * 68 + cc]     = Sa[nt][2];
            Ss[(wm0 + gr + 8) * 68 + cc + 1] = Sa[nt][3];
        }
        __syncthreads();

        // softmax: 4 threads per row, 16 cols each; P -> bf16
        {
            int row = tid >> 2;
            int q = tid & 3;
            const float* rp = &Ss[row * 68 + q * 16];
            float e[16];
            float mx = -INFINITY;
#pragma unroll
            for (int u4 = 0; u4 < 4; u4++) {
                float4 v = *(const float4*)&rp[u4 * 4];
                e[u4 * 4 + 0] = v.x; e[u4 * 4 + 1] = v.y;
                e[u4 * 4 + 2] = v.z; e[u4 * 4 + 3] = v.w;
                mx = fmaxf(mx, fmaxf(fmaxf(v.x, v.y), fmaxf(v.z, v.w)));
            }
            mx = fmaxf(mx, __shfl_xor_sync(0xffffffffu, mx, 1));
            mx = fmaxf(mx, __shfl_xor_sync(0xffffffffu, mx, 2));
            float mold = m_s[row];
            float mnew = fmaxf(mold, mx);
            float rsum = 0.f;
            __nv_bfloat16* pw = &Ps[row * 72 + q * 16];
#pragma unroll
            for (int u = 0; u < 8; u++) {
                float p0 = __expf(e[2 * u] - mnew);
                float p1 = __expf(e[2 * u + 1] - mnew);
                rsum += p0 + p1;
                *(uint32_t*)&pw[2 * u] = pack_bf16(p0, p1);
            }
            rsum += __shfl_xor_sync(0xffffffffu, rsum, 1);
            rsum += __shfl_xor_sync(0xffffffffu, rsum, 2);
            if (q == 0) {
                float corr = __expf(mold - mnew);
                l_s[row] = l_s[row] * corr + rsum;
                m_s[row] = mnew;
                corr_s[row] = corr;
            }
        }
        __syncthreads();

        // rescale O, then O += P V
        float cr0 = corr_s[wm0 + gr];
        float cr1 = corr_s[wm0 + gr + 8];
#pragma unroll
        for (int nt = 0; nt < 4; nt++) {
            O[nt][0] *= cr0; O[nt][1] *= cr0;
            O[nt][2] *= cr1; O[nt][3] *= cr1;
        }
#pragma unroll
        for (int kk = 0; kk < 64; kk += 16) {
            uint32_t a0 = *(const uint32_t*)&Ps[(wm0 + gr) * 72 + kk + gc * 2];
            uint32_t a1 = *(const uint32_t*)&Ps[(wm0 + gr + 8) * 72 + kk + gc * 2];
            uint32_t a2 = *(const uint32_t*)&Ps[(wm0 + gr) * 72 + kk + gc * 2 + 8];
            uint32_t a3 = *(const uint32_t*)&Ps[(wm0 + gr + 8) * 72 + kk + gc * 2 + 8];
#pragma unroll
            for (int nt = 0; nt < 4; nt++) {
                int n = wn0 + nt * 8 + gr;
                uint32_t b0 = *(const uint32_t*)&Vs[n * 72 + kk + gc * 2];
                uint32_t b1 = *(const uint32_t*)&Vs[n * 72 + kk + gc * 2 + 8];
                MMA_BF16(O[nt], a0, a1, a2, a3, b0, b1);
            }
        }
    }

    // normalize + write straight to aT [b][t0+t][h*64 + c] (O is [t][c])
    {
        float inv0 = 1.f / l_s[wm0 + gr];
        float inv1 = 1.f / l_s[wm0 + gr + 8];
        float* ap = aT + ((size_t)b * 1024 + t0) * 512 + h * 64;
#pragma unroll
        for (int nt = 0; nt < 4; nt++) {
            int cc = wn0 + nt * 8 + gc * 2;
            *(float2*)&ap[(size_t)(wm0 + gr) * 512 + cc] =
                make_float2(O[nt][0] * inv0, O[nt][1] * inv0);
            *(float2*)&ap[(size_t)(wm0 + gr + 8) * 512 + cc] =
                make_float2(O[nt][2] * inv1, O[nt][3] * inv1);
        }
    }
}

// ---------------- launch ----------------------------------------------------
extern "C" void kernel_launch(void* const* d_in, const int* in_sizes, int n_in,
                              void* d_out, int out_size) {
    const float* x      = (const float*)d_in[0];
    const float* gamma  = (const float*)d_in[1];
    const float* beta   = (const float*)d_in[2];
    const float* w_qkv  = (const float*)d_in[3];
    const float* b_qkv  = (const float*)d_in[4];
    const float* w_proj = (const float*)d_in[5];
    const float* b_proj = (const float*)d_in[6];
    float* out = (float*)d_out;

    float *hT_ptr, *qkv_ptr, *aT_ptr, *qT_ptr, *kT_ptr;
    cudaGetSymbolAddress((void**)&hT_ptr, g_hT);
    cudaGetSymbolAddress((void**)&qkv_ptr, g_qkv);
    cudaGetSymbolAddress((void**)&aT_ptr, g_aT);
    cudaGetSymbolAddress((void**)&qT_ptr, g_qT);
    cudaGetSymbolAddress((void**)&kT_ptr, g_kT);

    // 1) GroupNorm -> hT [b][t][c]
    groupnorm_t_kernel<<<8 * 32, 256>>>(x, gamma, beta, hT_ptr);

    // 2) QKV GEMM (bf16): q/k -> transposed buffers, v -> qkv buffer
    gemm_bf16_kernel<<<dim3(8, 12, 8), 256>>>(w_qkv, hT_ptr, b_qkv, nullptr,
                                              qkv_ptr, qT_ptr, kT_ptr,
                                              1536, 512);

    // 3) Attention (bf16 tensor cores) -> aT [b][t][c]
    cudaFuncSetAttribute(attn_bf16_kernel,
                         cudaFuncAttributeMaxDynamicSharedMemorySize, 55040);
    attn_bf16_kernel<<<dim3(16, 64), 256, 55040>>>(qT_ptr, kT_ptr, qkv_ptr,
                                                   aT_ptr);

    // 4) Proj GEMM + bias + residual (bf16)
    gemm_bf16_kernel<<<dim3(8, 4, 8), 256>>>(w_proj, aT_ptr, b_proj, x,
                                             out, nullptr, nullptr, 512, 512);
}

// round 8
// speedup vs baseline: 4.7155x; 1.2193x over previous
#include <cuda_runtime.h>
#include <cuda_bf16.h>
#include <math.h>
#include <stdint.h>

// ---------------- scratch (static device globals; no allocation) ------------
__device__ __nv_bfloat16 g_wqkv[1536 * 512];     // w_qkv bf16
__device__ __nv_bfloat16 g_wproj[512 * 512];     // w_proj bf16
__device__ __nv_bfloat16 g_hT[8 * 1024 * 512];   // groupnorm out [b][t][c]
__device__ __nv_bfloat16 g_qT[64 * 1024 * 64];   // Q [bh][t][c] (pre-scaled 1/8)
__device__ __nv_bfloat16 g_kT[64 * 1024 * 64];   // K [bh][s][c]
__device__ __nv_bfloat16 g_v[64 * 64 * 1024];    // V [bh][c][t]
__device__ __nv_bfloat16 g_aT[8 * 1024 * 512];   // attention out [b][t][c]

__device__ __forceinline__ uint32_t pack_bf16(float lo, float hi) {
    uint32_t r;
    asm("cvt.rn.bf16x2.f32 %0, %1, %2;" : "=r"(r) : "f"(hi), "f"(lo));
    return r;
}
__device__ __forceinline__ uint32_t su32(const void* p) {
    return (uint32_t)__cvta_generic_to_shared(p);
}
__device__ __forceinline__ void cp16(uint32_t dst, const void* src) {
    asm volatile("cp.async.ca.shared.global [%0], [%1], 16;" :: "r"(dst), "l"(src));
}
#define CP_COMMIT() asm volatile("cp.async.commit_group;")
#define CP_WAIT1()  asm volatile("cp.async.wait_group 1;")

#define MMA_BF16(c, a0, a1, a2, a3, b0, b1)                                   \
    asm volatile(                                                             \
        "mma.sync.aligned.m16n8k16.row.col.f32.bf16.bf16.f32 "                \
        "{%0,%1,%2,%3}, {%4,%5,%6,%7}, {%8,%9}, {%0,%1,%2,%3};"               \
        : "+f"((c)[0]), "+f"((c)[1]), "+f"((c)[2]), "+f"((c)[3])              \
        : "r"(a0), "r"(a1), "r"(a2), "r"(a3), "r"(b0), "r"(b1))

#define LDSM_X4(r0, r1, r2, r3, addr)                                         \
    asm volatile("ldmatrix.sync.aligned.m8n8.x4.shared.b16 {%0,%1,%2,%3}, [%4];" \
                 : "=r"(r0), "=r"(r1), "=r"(r2), "=r"(r3) : "r"(addr))
#define LDSM_X2(r0, r1, addr)                                                 \
    asm volatile("ldmatrix.sync.aligned.m8n8.x2.shared.b16 {%0,%1}, [%2];"    \
                 : "=r"(r0), "=r"(r1) : "r"(addr))

// ---------------- fp32 -> bf16 convert (weights) ----------------------------
__global__ void f2bf_kernel(const float* __restrict__ in,
                            __nv_bfloat16* __restrict__ out, int n4) {
    int i = blockIdx.x * 256 + threadIdx.x;
    if (i < n4) {
        float4 v = ((const float4*)in)[i];
        *(uint2*)&out[i * 4] =
            make_uint2(pack_bf16(v.x, v.y), pack_bf16(v.z, v.w));
    }
}

// ---------------- GroupNorm (writes transposed bf16 hT [b][t][c]) -----------
__global__ void groupnorm_t_kernel(const float* __restrict__ x,
                                   const float* __restrict__ gamma,
                                   const float* __restrict__ beta,
                                   __nv_bfloat16* __restrict__ hT) {
    int b = blockIdx.x >> 5;
    int g = blockIdx.x & 31;
    const float* xp = x + ((size_t)b * 512 + g * 16) * 1024;
    int tid = threadIdx.x;

    float s = 0.f, ss = 0.f;
    for (int e = tid; e < 16 * 1024; e += 256) {
        float v = xp[e];
        s += v; ss += v * v;
    }
    __shared__ float rs[256], rss[256];
    __shared__ float Ts[64][20];
    rs[tid] = s; rss[tid] = ss;
    __syncthreads();
    for (int o = 128; o > 0; o >>= 1) {
        if (tid < o) { rs[tid] += rs[tid + o]; rss[tid] += rss[tid + o]; }
        __syncthreads();
    }
    float mean = rs[0] * (1.f / 16384.f);
    float var  = rss[0] * (1.f / 16384.f) - mean * mean;
    float inv  = rsqrtf(var + 1e-5f);

    int cl = tid >> 4;
    int tw4 = (tid & 15) * 4;
    float scale = inv * gamma[g * 16 + cl];
    float shift = beta[g * 16 + cl] - mean * scale;
    __nv_bfloat16* hTb = hT + (size_t)b * 1024 * 512 + g * 16;
    int tr = tid >> 2, q = tid & 3;

    for (int t0 = 0; t0 < 1024; t0 += 64) {
        float4 v = *(const float4*)&xp[cl * 1024 + t0 + tw4];
        Ts[tw4 + 0][cl] = v.x * scale + shift;
        Ts[tw4 + 1][cl] = v.y * scale + shift;
        Ts[tw4 + 2][cl] = v.z * scale + shift;
        Ts[tw4 + 3][cl] = v.w * scale + shift;
        __syncthreads();
        *(uint2*)&hTb[(size_t)(t0 + tr) * 512 + q * 4] =
            make_uint2(pack_bf16(Ts[tr][q * 4 + 0], Ts[tr][q * 4 + 1]),
                       pack_bf16(Ts[tr][q * 4 + 2], Ts[tr][q * 4 + 3]));
        __syncthreads();
    }
}

// ---------------- BF16 GEMM: cp.async 3-stage + ldmatrix ---------------------
// C[b](M x 1024) = W (M x K) @ BT[b]^T ; BT is [1024][K] (n-major, k contig)
// Block 128x128, BK=64, 256 threads (8 warps 2x4), warp tile 64x32.
#define GSTRIDE 72
#define GTILE (128 * GSTRIDE)
extern __shared__ __nv_bfloat16 dyn_smem[];

__global__ __launch_bounds__(256, 2)
void gemm_bf16_async(const __nv_bfloat16* __restrict__ W,
                     const __nv_bfloat16* __restrict__ BT,
                     const float* __restrict__ bias,
                     const float* __restrict__ resid,
                     float* __restrict__ Cout,
                     __nv_bfloat16* __restrict__ qTp,
                     __nv_bfloat16* __restrict__ kTp,
                     __nv_bfloat16* __restrict__ vp,
                     int M, int Kdim) {
    __nv_bfloat16* As = dyn_smem;
    __nv_bfloat16* Bs = dyn_smem + 3 * GTILE;

    int bz = blockIdx.z;
    const __nv_bfloat16* Bp = BT + (size_t)bz * 1024 * Kdim;

    int m0 = blockIdx.y * 128, n0 = blockIdx.x * 128;
    int tid = threadIdx.x;
    int wid = tid >> 5, lane = tid & 31;
    int warp_m = wid >> 2, warp_n = wid & 3;
    int wm0 = warp_m * 64, wn0 = warp_n * 32;
    int gr = lane >> 2, gc = lane & 3;

    int ldr = tid >> 3;          // 0..31 (+i*32)
    int ldc = (tid & 7) * 8;     // 0..56
    uint32_t aU = su32(As), bU = su32(Bs);

    auto prefetch = [&](int kt, int st) {
        const __nv_bfloat16* wsrc = W + (size_t)m0 * Kdim + kt * 64 + ldc;
        const __nv_bfloat16* bsrc = Bp + (size_t)n0 * Kdim + kt * 64 + ldc;
        uint32_t aDst = aU + (uint32_t)(st * GTILE) * 2;
        uint32_t bDst = bU + (uint32_t)(st * GTILE) * 2;
#pragma unroll
        for (int i = 0; i < 4; i++) {
            int r = ldr + i * 32;
            cp16(aDst + (r * GSTRIDE + ldc) * 2, wsrc + (size_t)r * Kdim);
            cp16(bDst + (r * GSTRIDE + ldc) * 2, bsrc + (size_t)r * Kdim);
        }
        CP_COMMIT();
    };

    int ktiles = Kdim >> 6;
    prefetch(0, 0);
    prefetch(1, 1);

    float acc[4][4][4] = {};
    int aRow = lane & 15, aK = (lane >> 4) * 8;
    int bRow = lane & 7,  bK = ((lane >> 3) & 1) * 8;
    int aOff[4], bOff[4];
#pragma unroll
    for (int mt = 0; mt < 4; mt++) aOff[mt] = (wm0 + mt * 16 + aRow) * GSTRIDE + aK;
#pragma unroll
    for (int nt = 0; nt < 4; nt++) bOff[nt] = (wn0 + nt * 8 + bRow) * GSTRIDE + bK;

    for (int kt = 0; kt < ktiles; kt++) {
        CP_WAIT1();
        __syncthreads();
        if (kt + 2 < ktiles) prefetch(kt + 2, (kt + 2) % 3);
        int st = kt % 3;
        uint32_t aB = aU + (uint32_t)(st * GTILE) * 2;
        uint32_t bB = bU + (uint32_t)(st * GTILE) * 2;
#pragma unroll
        for (int kk = 0; kk < 64; kk += 16) {
            uint32_t af[4][4], bf[4][2];
#pragma unroll
            for (int mt = 0; mt < 4; mt++)
                LDSM_X4(af[mt][0], af[mt][1], af[mt][2], af[mt][3],
                        aB + (uint32_t)(aOff[mt] + kk) * 2);
#pragma unroll
            for (int nt = 0; nt < 4; nt++)
                LDSM_X2(bf[nt][0], bf[nt][1], bB + (uint32_t)(bOff[nt] + kk) * 2);
#pragma unroll
            for (int mt = 0; mt < 4; mt++)
#pragma unroll
                for (int nt = 0; nt < 4; nt++)
                    MMA_BF16(acc[mt][nt], af[mt][0], af[mt][1], af[mt][2],
                             af[mt][3], bf[nt][0], bf[nt][1]);
        }
    }

    if (qTp) {
        // qkv mode: scatter q (scaled 1/8) / k / v to bf16 buffers
#pragma unroll
        for (int mt = 0; mt < 4; mt++)
#pragma unroll
            for (int nt = 0; nt < 4; nt++) {
                int r0 = m0 + wm0 + mt * 16 + gr;
                int cc = n0 + wn0 + nt * 8 + gc * 2;
                float bv0 = bias[r0], bv1 = bias[r0 + 8];
                float* c = acc[mt][nt];
#pragma unroll
                for (int e = 0; e < 4; e++) {
                    int m = r0 + ((e >> 1) << 3);
                    int n = cc + (e & 1);
                    float val = c[e] + ((e >> 1) ? bv1 : bv0);
                    int head = m / 192;
                    int r = m - head * 192;
                    size_t bh = (size_t)(bz * 8 + head);
                    if (r < 64)
                        qTp[(bh * 1024 + n) * 64 + r] = __float2bfloat16(val * 0.125f);
                    else if (r < 128)
                        kTp[(bh * 1024 + n) * 64 + (r - 64)] = __float2bfloat16(val);
                    else
                        vp[(bh * 64 + (r - 128)) * 1024 + n] = __float2bfloat16(val);
                }
            }
    } else {
        float* Cp = Cout + (size_t)bz * M * 1024;
        const float* Rp = resid + (size_t)bz * M * 1024;
#pragma unroll
        for (int mt = 0; mt < 4; mt++)
#pragma unroll
            for (int nt = 0; nt < 4; nt++) {
                int r0 = m0 + wm0 + mt * 16 + gr;
                int cc = n0 + wn0 + nt * 8 + gc * 2;
                float bv0 = bias[r0], bv1 = bias[r0 + 8];
                float* c = acc[mt][nt];
                size_t off0 = (size_t)r0 * 1024 + cc;
                size_t off1 = (size_t)(r0 + 8) * 1024 + cc;
                float2 r0v = *(const float2*)&Rp[off0];
                float2 r1v = *(const float2*)&Rp[off1];
                *(float2*)&Cp[off0] =
                    make_float2(c[0] + bv0 + r0v.x, c[1] + bv0 + r0v.y);
                *(float2*)&Cp[off1] =
                    make_float2(c[2] + bv1 + r1v.x, c[3] + bv1 + r1v.y);
            }
    }
}

// ---------------- BF16 flash attention (ldmatrix + reg prefetch) -------------
// Block: 64 t-rows of one (b,h). 8 warps (4m x 2n), warp tile 16x32.
extern __shared__ char attn_smem[];
__global__ __launch_bounds__(256, 2)
void attn_bf16_kernel(const __nv_bfloat16* __restrict__ qT,
                      const __nv_bfloat16* __restrict__ kT,
                      const __nv_bfloat16* __restrict__ vb,
                      __nv_bfloat16* __restrict__ aT) {
    __nv_bfloat16* Qt = (__nv_bfloat16*)attn_smem;   // [64][72] t x c
    __nv_bfloat16* Kt = Qt + 64 * 72;                // [64][72] s x c
    __nv_bfloat16* Vs = Kt + 64 * 72;                // [64][72] c x s
    __nv_bfloat16* Ps = Vs + 64 * 72;                // [64][72] t x s
    float* Ss = (float*)(Ps + 64 * 72);              // [64][68] fp32
    float* m_s = Ss + 64 * 68;
    float* l_s = m_s + 64;
    float* corr_s = l_s + 64;

    int bh = blockIdx.y;
    int b = bh >> 3, h = bh & 7;
    int t0 = blockIdx.x * 64;
    const __nv_bfloat16* Qp = qT + (size_t)bh * 1024 * 64;
    const __nv_bfloat16* Kp = kT + (size_t)bh * 1024 * 64;
    const __nv_bfloat16* Vp = vb + (size_t)bh * 64 * 1024;

    int tid = threadIdx.x;
    int wid = tid >> 5, lane = tid & 31;
    int warp_m = wid >> 1, warp_n = wid & 1;
    int wm0 = warp_m * 16, wn0 = warp_n * 32;
    int gr = lane >> 2, gc = lane & 3;
    int ldr = tid >> 3, ldc = (tid & 7) * 8;

    // Q tile [t][c] (already scaled at qkv epilogue)
#pragma unroll
    for (int it = 0; it < 2; it++) {
        int r = ldr + it * 32;
        *(uint4*)&Qt[r * 72 + ldc] = *(const uint4*)&Qp[(size_t)(t0 + r) * 64 + ldc];
    }
    if (tid < 64) { m_s[tid] = -INFINITY; l_s[tid] = 0.f; }

    // prefetch first K/V tiles into registers
    uint4 kreg[2], vreg[2];
#pragma unroll
    for (int it = 0; it < 2; it++) {
        int r = ldr + it * 32;
        kreg[it] = *(const uint4*)&Kp[(size_t)r * 64 + ldc];
        vreg[it] = *(const uint4*)&Vp[(size_t)r * 1024 + ldc];
    }

    uint32_t qU = su32(Qt), kU = su32(Kt), vU = su32(Vs), pU = su32(Ps);
    int aRow = lane & 15, aK = (lane >> 4) * 8;
    int bRow = lane & 7,  bK = ((lane >> 3) & 1) * 8;
    int aOff = (wm0 + aRow) * 72 + aK;
    int bOff[4];
#pragma unroll
    for (int nt = 0; nt < 4; nt++) bOff[nt] = (wn0 + nt * 8 + bRow) * 72 + bK;

    float O[4][4] = {};

    for (int s0 = 0; s0 < 1024; s0 += 64) {
        __syncthreads();   // prior Ps/Vs reads done; Q/init visible (first iter)
#pragma unroll
        for (int it = 0; it < 2; it++) {
            int r = ldr + it * 32;
            *(uint4*)&Kt[r * 72 + ldc] = kreg[it];
            *(uint4*)&Vs[r * 72 + ldc] = vreg[it];
        }
        __syncthreads();
        if (s0 + 64 < 1024) {
            int sn = s0 + 64;
#pragma unroll
            for (int it = 0; it < 2; it++) {
                int r = ldr + it * 32;
                kreg[it] = *(const uint4*)&Kp[(size_t)(sn + r) * 64 + ldc];
                vreg[it] = *(const uint4*)&Vp[(size_t)r * 1024 + sn + ldc];
            }
        }

        // S = Q K^T
        float Sa[4][4] = {};
#pragma unroll
        for (int kk = 0; kk < 64; kk += 16) {
            uint32_t a0, a1, a2, a3;
            LDSM_X4(a0, a1, a2, a3, qU + (uint32_t)(aOff + kk) * 2);
#pragma unroll
            for (int nt = 0; nt < 4; nt++) {
                uint32_t b0, b1;
                LDSM_X2(b0, b1, kU + (uint32_t)(bOff[nt] + kk) * 2);
                MMA_BF16(Sa[nt], a0, a1, a2, a3, b0, b1);
            }
        }
#pragma unroll
        for (int nt = 0; nt < 4; nt++) {
            int cc = wn0 + nt * 8 + gc * 2;
            Ss[(wm0 + gr) * 68 + cc]         = Sa[nt][0];
            Ss[(wm0 + gr) * 68 + cc + 1]     = Sa[nt][1];
            Ss[(wm0 + gr + 8) * 68 + cc]     = Sa[nt][2];
            Ss[(wm0 + gr + 8) * 68 + cc + 1] = Sa[nt][3];
        }
        __syncthreads();

        // softmax: 4 threads per row, 16 cols each; P -> bf16
        {
            int row = tid >> 2;
            int q = tid & 3;
            const float* rp = &Ss[row * 68 + q * 16];
            float e[16];
            float mx = -INFINITY;
#pragma unroll
            for (int u4 = 0; u4 < 4; u4++) {
                float4 v = *(const float4*)&rp[u4 * 4];
                e[u4 * 4 + 0] = v.x; e[u4 * 4 + 1] = v.y;
                e[u4 * 4 + 2] = v.z; e[u4 * 4 + 3] = v.w;
                mx = fmaxf(mx, fmaxf(fmaxf(v.x, v.y), fmaxf(v.z, v.w)));
            }
            mx = fmaxf(mx, __shfl_xor_sync(0xffffffffu, mx, 1));
            mx = fmaxf(mx, __shfl_xor_sync(0xffffffffu, mx, 2));
            float mold = m_s[row];
            float mnew = fmaxf(mold, mx);
            float rsum = 0.f;
            __nv_bfloat16* pw = &Ps[row * 72 + q * 16];
#pragma unroll
            for (int u = 0; u < 8; u++) {
                float p0 = __expf(e[2 * u] - mnew);
                float p1 = __expf(e[2 * u + 1] - mnew);
                rsum += p0 + p1;
                *(uint32_t*)&pw[2 * u] = pack_bf16(p0, p1);
            }
            rsum += __shfl_xor_sync(0xffffffffu, rsum, 1);
            rsum += __shfl_xor_sync(0xffffffffu, rsum, 2);
            if (q == 0) {
                float corr = __expf(mold - mnew);
                l_s[row] = l_s[row] * corr + rsum;
                m_s[row] = mnew;
                corr_s[row] = corr;
            }
        }
        __syncthreads();

        // rescale O, then O += P V
        float cr0 = corr_s[wm0 + gr];
        float cr1 = corr_s[wm0 + gr + 8];
#pragma unroll
        for (int nt = 0; nt < 4; nt++) {
            O[nt][0] *= cr0; O[nt][1] *= cr0;
            O[nt][2] *= cr1; O[nt][3] *= cr1;
        }
#pragma unroll
        for (int kk = 0; kk < 64; kk += 16) {
            uint32_t a0, a1, a2, a3;
            LDSM_X4(a0, a1, a2, a3, pU + (uint32_t)(aOff + kk) * 2);
#pragma unroll
            for (int nt = 0; nt < 4; nt++) {
                uint32_t b0, b1;
                LDSM_X2(b0, b1, vU + (uint32_t)(bOff[nt] + kk) * 2);
                MMA_BF16(O[nt], a0, a1, a2, a3, b0, b1);
            }
        }
    }

    // normalize + write bf16 aT [b][t0+t][h*64+c] (O is [t][c])
    {
        float inv0 = 1.f / l_s[wm0 + gr];
        float inv1 = 1.f / l_s[wm0 + gr + 8];
        __nv_bfloat16* ap = aT + ((size_t)b * 1024 + t0) * 512 + h * 64;
#pragma unroll
        for (int nt = 0; nt < 4; nt++) {
            int cc = wn0 + nt * 8 + gc * 2;
            *(uint32_t*)&ap[(size_t)(wm0 + gr) * 512 + cc] =
                pack_bf16(O[nt][0] * inv0, O[nt][1] * inv0);
            *(uint32_t*)&ap[(size_t)(wm0 + gr + 8) * 512 + cc] =
                pack_bf16(O[nt][2] * inv1, O[nt][3] * inv1);
        }
    }
}

// ---------------- launch ----------------------------------------------------
extern "C" void kernel_launch(void* const* d_in, const int* in_sizes, int n_in,
                              void* d_out, int out_size) {
    const float* x      = (const float*)d_in[0];
    const float* gamma  = (const float*)d_in[1];
    const float* beta   = (const float*)d_in[2];
    const float* w_qkv  = (const float*)d_in[3];
    const float* b_qkv  = (const float*)d_in[4];
    const float* w_proj = (const float*)d_in[5];
    const float* b_proj = (const float*)d_in[6];
    float* out = (float*)d_out;

    __nv_bfloat16 *wqkv_p, *wproj_p, *hT_p, *qT_p, *kT_p, *v_p, *aT_p;
    cudaGetSymbolAddress((void**)&wqkv_p, g_wqkv);
    cudaGetSymbolAddress((void**)&wproj_p, g_wproj);
    cudaGetSymbolAddress((void**)&hT_p, g_hT);
    cudaGetSymbolAddress((void**)&qT_p, g_qT);
    cudaGetSymbolAddress((void**)&kT_p, g_kT);
    cudaGetSymbolAddress((void**)&v_p, g_v);
    cudaGetSymbolAddress((void**)&aT_p, g_aT);

    // 0) convert weights to bf16
    f2bf_kernel<<<768, 256>>>(w_qkv, wqkv_p, 196608);
    f2bf_kernel<<<256, 256>>>(w_proj, wproj_p, 65536);

    // 1) GroupNorm -> hT bf16 [b][t][c]
    groupnorm_t_kernel<<<8 * 32, 256>>>(x, gamma, beta, hT_p);

    // 2) QKV GEMM (bf16, async): q(scaled)/k/v -> bf16 buffers
    cudaFuncSetAttribute(gemm_bf16_async,
                         cudaFuncAttributeMaxDynamicSharedMemorySize, 110592);
    gemm_bf16_async<<<dim3(8, 12, 8), 256, 110592>>>(
        wqkv_p, hT_p, b_qkv, nullptr, nullptr, qT_p, kT_p, v_p, 1536, 512);

    // 3) Attention -> aT bf16
    cudaFuncSetAttribute(attn_bf16_kernel,
                         cudaFuncAttributeMaxDynamicSharedMemorySize, 55040);
    attn_bf16_kernel<<<dim3(16, 64), 256, 55040>>>(qT_p, kT_p, v_p, aT_p);

    // 4) Proj GEMM + bias + residual -> fp32 out
    gemm_bf16_async<<<dim3(8, 4, 8), 256, 110592>>>(
        wproj_p, aT_p, b_proj, x, out, nullptr, nullptr, nullptr, 512, 512);
}

// round 9
// speedup vs baseline: 6.0241x; 1.2775x over previous
#include <cuda_runtime.h>
#include <cuda_bf16.h>
#include <math.h>
#include <stdint.h>

// ---------------- scratch (static device globals; no allocation) ------------
__device__ __nv_bfloat16 g_wqkv[1536 * 512];     // w_qkv bf16
__device__ __nv_bfloat16 g_wproj[512 * 512];     // w_proj bf16
__device__ __nv_bfloat16 g_hT[8 * 1024 * 512];   // groupnorm out [b][t][c]
__device__ __nv_bfloat16 g_qT[64 * 1024 * 64];   // Q [bh][t][c] (pre-scaled 1/8)
__device__ __nv_bfloat16 g_kT[64 * 1024 * 64];   // K [bh][s][c]
__device__ __nv_bfloat16 g_v[64 * 64 * 1024];    // V [bh][c][t]
__device__ __nv_bfloat16 g_aT[8 * 1024 * 512];   // attention out [b][t][c]

__device__ __forceinline__ uint32_t pack_bf16(float lo, float hi) {
    uint32_t r;
    asm("cvt.rn.bf16x2.f32 %0, %1, %2;" : "=r"(r) : "f"(hi), "f"(lo));
    return r;
}
__device__ __forceinline__ uint32_t su32(const void* p) {
    return (uint32_t)__cvta_generic_to_shared(p);
}
__device__ __forceinline__ void cp16(uint32_t dst, const void* src) {
    asm volatile("cp.async.ca.shared.global [%0], [%1], 16;" :: "r"(dst), "l"(src));
}
#define CP_COMMIT() asm volatile("cp.async.commit_group;")
#define CP_WAIT1()  asm volatile("cp.async.wait_group 1;")

#define MMA_BF16(c, a0, a1, a2, a3, b0, b1)                                   \
    asm volatile(                                                             \
        "mma.sync.aligned.m16n8k16.row.col.f32.bf16.bf16.f32 "                \
        "{%0,%1,%2,%3}, {%4,%5,%6,%7}, {%8,%9}, {%0,%1,%2,%3};"               \
        : "+f"((c)[0]), "+f"((c)[1]), "+f"((c)[2]), "+f"((c)[3])              \
        : "r"(a0), "r"(a1), "r"(a2), "r"(a3), "r"(b0), "r"(b1))

#define LDSM_X4(r0, r1, r2, r3, addr)                                         \
    asm volatile("ldmatrix.sync.aligned.m8n8.x4.shared.b16 {%0,%1,%2,%3}, [%4];" \
                 : "=r"(r0), "=r"(r1), "=r"(r2), "=r"(r3) : "r"(addr))
#define LDSM_X2(r0, r1, addr)                                                 \
    asm volatile("ldmatrix.sync.aligned.m8n8.x2.shared.b16 {%0,%1}, [%2];"    \
                 : "=r"(r0), "=r"(r1) : "r"(addr))

// ---------------- fp32 -> bf16 convert (weights) ----------------------------
__global__ void f2bf_kernel(const float* __restrict__ in,
                            __nv_bfloat16* __restrict__ out, int n4) {
    int i = blockIdx.x * 256 + threadIdx.x;
    if (i < n4) {
        float4 v = ((const float4*)in)[i];
        *(uint2*)&out[i * 4] =
            make_uint2(pack_bf16(v.x, v.y), pack_bf16(v.z, v.w));
    }
}

// ---------------- GroupNorm (writes transposed bf16 hT [b][t][c]) -----------
__global__ void groupnorm_t_kernel(const float* __restrict__ x,
                                   const float* __restrict__ gamma,
                                   const float* __restrict__ beta,
                                   __nv_bfloat16* __restrict__ hT) {
    int b = blockIdx.x >> 5;
    int g = blockIdx.x & 31;
    const float* xp = x + ((size_t)b * 512 + g * 16) * 1024;
    int tid = threadIdx.x;

    float s = 0.f, ss = 0.f;
    for (int e = tid; e < 16 * 1024; e += 256) {
        float v = xp[e];
        s += v; ss += v * v;
    }
    __shared__ float rs[256], rss[256];
    __shared__ float Ts[64][20];
    rs[tid] = s; rss[tid] = ss;
    __syncthreads();
    for (int o = 128; o > 0; o >>= 1) {
        if (tid < o) { rs[tid] += rs[tid + o]; rss[tid] += rss[tid + o]; }
        __syncthreads();
    }
    float mean = rs[0] * (1.f / 16384.f);
    float var  = rss[0] * (1.f / 16384.f) - mean * mean;
    float inv  = rsqrtf(var + 1e-5f);

    int cl = tid >> 4;
    int tw4 = (tid & 15) * 4;
    float scale = inv * gamma[g * 16 + cl];
    float shift = beta[g * 16 + cl] - mean * scale;
    __nv_bfloat16* hTb = hT + (size_t)b * 1024 * 512 + g * 16;
    int tr = tid >> 2, q = tid & 3;

    for (int t0 = 0; t0 < 1024; t0 += 64) {
        float4 v = *(const float4*)&xp[cl * 1024 + t0 + tw4];
        Ts[tw4 + 0][cl] = v.x * scale + shift;
        Ts[tw4 + 1][cl] = v.y * scale + shift;
        Ts[tw4 + 2][cl] = v.z * scale + shift;
        Ts[tw4 + 3][cl] = v.w * scale + shift;
        __syncthreads();
        *(uint2*)&hTb[(size_t)(t0 + tr) * 512 + q * 4] =
            make_uint2(pack_bf16(Ts[tr][q * 4 + 0], Ts[tr][q * 4 + 1]),
                       pack_bf16(Ts[tr][q * 4 + 2], Ts[tr][q * 4 + 3]));
        __syncthreads();
    }
}

// ---------------- BF16 GEMM: cp.async 3-stage + ldmatrix ---------------------
#define GSTRIDE 72
#define GTILE (128 * GSTRIDE)
extern __shared__ __nv_bfloat16 dyn_smem[];

__global__ __launch_bounds__(256, 2)
void gemm_bf16_async(const __nv_bfloat16* __restrict__ W,
                     const __nv_bfloat16* __restrict__ BT,
                     const float* __restrict__ bias,
                     const float* __restrict__ resid,
                     float* __restrict__ Cout,
                     __nv_bfloat16* __restrict__ qTp,
                     __nv_bfloat16* __restrict__ kTp,
                     __nv_bfloat16* __restrict__ vp,
                     int M, int Kdim) {
    __nv_bfloat16* As = dyn_smem;
    __nv_bfloat16* Bs = dyn_smem + 3 * GTILE;

    int bz = blockIdx.z;
    const __nv_bfloat16* Bp = BT + (size_t)bz * 1024 * Kdim;

    int m0 = blockIdx.y * 128, n0 = blockIdx.x * 128;
    int tid = threadIdx.x;
    int wid = tid >> 5, lane = tid & 31;
    int warp_m = wid >> 2, warp_n = wid & 3;
    int wm0 = warp_m * 64, wn0 = warp_n * 32;
    int gr = lane >> 2, gc = lane & 3;

    int ldr = tid >> 3;
    int ldc = (tid & 7) * 8;
    uint32_t aU = su32(As), bU = su32(Bs);

    auto prefetch = [&](int kt, int st) {
        const __nv_bfloat16* wsrc = W + (size_t)m0 * Kdim + kt * 64 + ldc;
        const __nv_bfloat16* bsrc = Bp + (size_t)n0 * Kdim + kt * 64 + ldc;
        uint32_t aDst = aU + (uint32_t)(st * GTILE) * 2;
        uint32_t bDst = bU + (uint32_t)(st * GTILE) * 2;
#pragma unroll
        for (int i = 0; i < 4; i++) {
            int r = ldr + i * 32;
            cp16(aDst + (r * GSTRIDE + ldc) * 2, wsrc + (size_t)r * Kdim);
            cp16(bDst + (r * GSTRIDE + ldc) * 2, bsrc + (size_t)r * Kdim);
        }
        CP_COMMIT();
    };

    int ktiles = Kdim >> 6;
    prefetch(0, 0);
    prefetch(1, 1);

    float acc[4][4][4] = {};
    int aRow = lane & 15, aK = (lane >> 4) * 8;
    int bRow = lane & 7,  bK = ((lane >> 3) & 1) * 8;
    int aOff[4], bOff[4];
#pragma unroll
    for (int mt = 0; mt < 4; mt++) aOff[mt] = (wm0 + mt * 16 + aRow) * GSTRIDE + aK;
#pragma unroll
    for (int nt = 0; nt < 4; nt++) bOff[nt] = (wn0 + nt * 8 + bRow) * GSTRIDE + bK;

    for (int kt = 0; kt < ktiles; kt++) {
        CP_WAIT1();
        __syncthreads();
        if (kt + 2 < ktiles) prefetch(kt + 2, (kt + 2) % 3);
        int st = kt % 3;
        uint32_t aB = aU + (uint32_t)(st * GTILE) * 2;
        uint32_t bB = bU + (uint32_t)(st * GTILE) * 2;
#pragma unroll
        for (int kk = 0; kk < 64; kk += 16) {
            uint32_t af[4][4], bf[4][2];
#pragma unroll
            for (int mt = 0; mt < 4; mt++)
                LDSM_X4(af[mt][0], af[mt][1], af[mt][2], af[mt][3],
                        aB + (uint32_t)(aOff[mt] + kk) * 2);
#pragma unroll
            for (int nt = 0; nt < 4; nt++)
                LDSM_X2(bf[nt][0], bf[nt][1], bB + (uint32_t)(bOff[nt] + kk) * 2);
#pragma unroll
            for (int mt = 0; mt < 4; mt++)
#pragma unroll
                for (int nt = 0; nt < 4; nt++)
                    MMA_BF16(acc[mt][nt], af[mt][0], af[mt][1], af[mt][2],
                             af[mt][3], bf[nt][0], bf[nt][1]);
        }
    }

    if (qTp) {
#pragma unroll
        for (int mt = 0; mt < 4; mt++)
#pragma unroll
            for (int nt = 0; nt < 4; nt++) {
                int r0 = m0 + wm0 + mt * 16 + gr;
                int cc = n0 + wn0 + nt * 8 + gc * 2;
                float bv0 = bias[r0], bv1 = bias[r0 + 8];
                float* c = acc[mt][nt];
#pragma unroll
                for (int e = 0; e < 4; e++) {
                    int m = r0 + ((e >> 1) << 3);
                    int n = cc + (e & 1);
                    float val = c[e] + ((e >> 1) ? bv1 : bv0);
                    int head = m / 192;
                    int r = m - head * 192;
                    size_t bh = (size_t)(bz * 8 + head);
                    if (r < 64)
                        qTp[(bh * 1024 + n) * 64 + r] = __float2bfloat16(val * 0.125f);
                    else if (r < 128)
                        kTp[(bh * 1024 + n) * 64 + (r - 64)] = __float2bfloat16(val);
                    else
                        vp[(bh * 64 + (r - 128)) * 1024 + n] = __float2bfloat16(val);
                }
            }
    } else {
        float* Cp = Cout + (size_t)bz * M * 1024;
        const float* Rp = resid + (size_t)bz * M * 1024;
#pragma unroll
        for (int mt = 0; mt < 4; mt++)
#pragma unroll
            for (int nt = 0; nt < 4; nt++) {
                int r0 = m0 + wm0 + mt * 16 + gr;
                int cc = n0 + wn0 + nt * 8 + gc * 2;
                float bv0 = bias[r0], bv1 = bias[r0 + 8];
                float* c = acc[mt][nt];
                size_t off0 = (size_t)r0 * 1024 + cc;
                size_t off1 = (size_t)(r0 + 8) * 1024 + cc;
                float2 r0v = *(const float2*)&Rp[off0];
                float2 r1v = *(const float2*)&Rp[off1];
                *(float2*)&Cp[off0] =
                    make_float2(c[0] + bv0 + r0v.x, c[1] + bv0 + r0v.y);
                *(float2*)&Cp[off1] =
                    make_float2(c[2] + bv1 + r1v.x, c[3] + bv1 + r1v.y);
            }
    }
}

// ---------------- BF16 flash attention: register-resident softmax ------------
// Block: 128 t-rows of one (b,h). 8 warps, each owns 16 t-rows x all 64 s-cols.
// S fragments reused directly as PV A-fragments (FA2 layout); softmax via shfl.
extern __shared__ char attn_smem[];
__global__ __launch_bounds__(256, 2)
void attn_bf16_kernel(const __nv_bfloat16* __restrict__ qT,
                      const __nv_bfloat16* __restrict__ kT,
                      const __nv_bfloat16* __restrict__ vb,
                      __nv_bfloat16* __restrict__ aT) {
    __nv_bfloat16* Qt = (__nv_bfloat16*)attn_smem;   // [128][72] t x c
    __nv_bfloat16* Kt = Qt + 128 * 72;               // [64][72]  s x c
    __nv_bfloat16* Vs = Kt + 64 * 72;                // [64][72]  c x s

    int bh = blockIdx.y;
    int b = bh >> 3, h = bh & 7;
    int t0 = blockIdx.x * 128;
    const __nv_bfloat16* Qp = qT + (size_t)bh * 1024 * 64;
    const __nv_bfloat16* Kp = kT + (size_t)bh * 1024 * 64;
    const __nv_bfloat16* Vp = vb + (size_t)bh * 64 * 1024;

    int tid = threadIdx.x;
    int wid = tid >> 5, lane = tid & 31;
    int wm0 = wid * 16;
    int gr = lane >> 2, gc = lane & 3;
    int ldr = tid >> 3, ldc = (tid & 7) * 8;

    // load Q tile [128][64] (pre-scaled by 1/8 at qkv epilogue)
#pragma unroll
    for (int it = 0; it < 4; it++) {
        int r = ldr + it * 32;
        *(uint4*)&Qt[r * 72 + ldc] = *(const uint4*)&Qp[(size_t)(t0 + r) * 64 + ldc];
    }

    // prefetch first K/V tiles
    uint4 kreg[2], vreg[2];
#pragma unroll
    for (int it = 0; it < 2; it++) {
        int r = ldr + it * 32;
        kreg[it] = *(const uint4*)&Kp[(size_t)r * 64 + ldc];
        vreg[it] = *(const uint4*)&Vp[(size_t)r * 1024 + ldc];
    }

    uint32_t qU = su32(Qt), kU = su32(Kt), vU = su32(Vs);
    int aRow = lane & 15, aK = (lane >> 4) * 8;
    int bRow = lane & 7,  bK = ((lane >> 3) & 1) * 8;
    int aOff = (wm0 + aRow) * 72 + aK;
    int bOff[8];
#pragma unroll
    for (int nt = 0; nt < 8; nt++) bOff[nt] = (nt * 8 + bRow) * 72 + bK;

    float O[8][4] = {};
    float m0 = -INFINITY, m1 = -INFINITY, l0 = 0.f, l1 = 0.f;

    for (int s0 = 0; s0 < 1024; s0 += 64) {
        __syncthreads();   // all PV/QK smem reads of prev iter done (and Q load)
#pragma unroll
        for (int it = 0; it < 2; it++) {
            int r = ldr + it * 32;
            *(uint4*)&Kt[r * 72 + ldc] = kreg[it];
            *(uint4*)&Vs[r * 72 + ldc] = vreg[it];
        }
        __syncthreads();
        if (s0 + 64 < 1024) {
            int sn = s0 + 64;
#pragma unroll
            for (int it = 0; it < 2; it++) {
                int r = ldr + it * 32;
                kreg[it] = *(const uint4*)&Kp[(size_t)(sn + r) * 64 + ldc];
                vreg[it] = *(const uint4*)&Vp[(size_t)r * 1024 + sn + ldc];
            }
        }

        // ---- S = Q K^T : warp tile 16 x 64 ----
        float S[8][4] = {};
#pragma unroll
        for (int kk = 0; kk < 64; kk += 16) {
            uint32_t a0, a1, a2, a3;
            LDSM_X4(a0, a1, a2, a3, qU + (uint32_t)(aOff + kk) * 2);
#pragma unroll
            for (int nt = 0; nt < 8; nt++) {
                uint32_t b0, b1;
                LDSM_X2(b0, b1, kU + (uint32_t)(bOff[nt] + kk) * 2);
                MMA_BF16(S[nt], a0, a1, a2, a3, b0, b1);
            }
        }

        // ---- softmax in registers (rows gr and gr+8) ----
        float mx0 = -INFINITY, mx1 = -INFINITY;
#pragma unroll
        for (int nt = 0; nt < 8; nt++) {
            mx0 = fmaxf(mx0, fmaxf(S[nt][0], S[nt][1]));
            mx1 = fmaxf(mx1, fmaxf(S[nt][2], S[nt][3]));
        }
        mx0 = fmaxf(mx0, __shfl_xor_sync(0xffffffffu, mx0, 1));
        mx0 = fmaxf(mx0, __shfl_xor_sync(0xffffffffu, mx0, 2));
        mx1 = fmaxf(mx1, __shfl_xor_sync(0xffffffffu, mx1, 1));
        mx1 = fmaxf(mx1, __shfl_xor_sync(0xffffffffu, mx1, 2));
        float mn0 = fmaxf(m0, mx0), mn1 = fmaxf(m1, mx1);
        float corr0 = __expf(m0 - mn0), corr1 = __expf(m1 - mn1);
        m0 = mn0; m1 = mn1;

        float rs0 = 0.f, rs1 = 0.f;
        uint32_t P[8][2];   // packed bf16 P fragments (reused as PV A-frags)
#pragma unroll
        for (int nt = 0; nt < 8; nt++) {
            float p0 = __expf(S[nt][0] - mn0);
            float p1 = __expf(S[nt][1] - mn0);
            float p2 = __expf(S[nt][2] - mn1);
            float p3 = __expf(S[nt][3] - mn1);
            rs0 += p0 + p1; rs1 += p2 + p3;
            P[nt][0] = pack_bf16(p0, p1);
            P[nt][1] = pack_bf16(p2, p3);
        }
        rs0 += __shfl_xor_sync(0xffffffffu, rs0, 1);
        rs0 += __shfl_xor_sync(0xffffffffu, rs0, 2);
        rs1 += __shfl_xor_sync(0xffffffffu, rs1, 1);
        rs1 += __shfl_xor_sync(0xffffffffu, rs1, 2);
        l0 = l0 * corr0 + rs0;
        l1 = l1 * corr1 + rs1;

        // ---- rescale O, then O += P V ----
#pragma unroll
        for (int nt = 0; nt < 8; nt++) {
            O[nt][0] *= corr0; O[nt][1] *= corr0;
            O[nt][2] *= corr1; O[nt][3] *= corr1;
        }
#pragma unroll
        for (int j = 0; j < 4; j++) {    // kk = 16j over s
            uint32_t a0 = P[2 * j][0], a1 = P[2 * j][1];
            uint32_t a2 = P[2 * j + 1][0], a3 = P[2 * j + 1][1];
#pragma unroll
            for (int nt = 0; nt < 8; nt++) {
                uint32_t b0, b1;
                LDSM_X2(b0, b1, vU + (uint32_t)(bOff[nt] + 16 * j) * 2);
                MMA_BF16(O[nt], a0, a1, a2, a3, b0, b1);
            }
        }
    }

    // ---- normalize + write bf16 aT [b][t0+t][h*64+c] ----
    {
        float inv0 = 1.f / l0, inv1 = 1.f / l1;
        __nv_bfloat16* ap = aT + ((size_t)b * 1024 + t0) * 512 + h * 64;
#pragma unroll
        for (int nt = 0; nt < 8; nt++) {
            int cc = nt * 8 + gc * 2;
            *(uint32_t*)&ap[(size_t)(wm0 + gr) * 512 + cc] =
                pack_bf16(O[nt][0] * inv0, O[nt][1] * inv0);
            *(uint32_t*)&ap[(size_t)(wm0 + gr + 8) * 512 + cc] =
                pack_bf16(O[nt][2] * inv1, O[nt][3] * inv1);
        }
    }
}

// ---------------- launch ----------------------------------------------------
extern "C" void kernel_launch(void* const* d_in, const int* in_sizes, int n_in,
                              void* d_out, int out_size) {
    const float* x      = (const float*)d_in[0];
    const float* gamma  = (const float*)d_in[1];
    const float* beta   = (const float*)d_in[2];
    const float* w_qkv  = (const float*)d_in[3];
    const float* b_qkv  = (const float*)d_in[4];
    const float* w_proj = (const float*)d_in[5];
    const float* b_proj = (const float*)d_in[6];
    float* out = (float*)d_out;

    __nv_bfloat16 *wqkv_p, *wproj_p, *hT_p, *qT_p, *kT_p, *v_p, *aT_p;
    cudaGetSymbolAddress((void**)&wqkv_p, g_wqkv);
    cudaGetSymbolAddress((void**)&wproj_p, g_wproj);
    cudaGetSymbolAddress((void**)&hT_p, g_hT);
    cudaGetSymbolAddress((void**)&qT_p, g_qT);
    cudaGetSymbolAddress((void**)&kT_p, g_kT);
    cudaGetSymbolAddress((void**)&v_p, g_v);
    cudaGetSymbolAddress((void**)&aT_p, g_aT);

    // 0) convert weights to bf16
    f2bf_kernel<<<768, 256>>>(w_qkv, wqkv_p, 196608);
    f2bf_kernel<<<256, 256>>>(w_proj, wproj_p, 65536);

    // 1) GroupNorm -> hT bf16 [b][t][c]
    groupnorm_t_kernel<<<8 * 32, 256>>>(x, gamma, beta, hT_p);

    // 2) QKV GEMM (bf16, async): q(scaled)/k/v -> bf16 buffers
    cudaFuncSetAttribute(gemm_bf16_async,
                         cudaFuncAttributeMaxDynamicSharedMemorySize, 110592);
    gemm_bf16_async<<<dim3(8, 12, 8), 256, 110592>>>(
        wqkv_p, hT_p, b_qkv, nullptr, nullptr, qT_p, kT_p, v_p, 1536, 512);

    // 3) Attention (register-resident softmax) -> aT bf16
    attn_bf16_kernel<<<dim3(8, 64), 256, 36864>>>(qT_p, kT_p, v_p, aT_p);

    // 4) Proj GEMM + bias + residual -> fp32 out
    gemm_bf16_async<<<dim3(8, 4, 8), 256, 110592>>>(
        wproj_p, aT_p, b_proj, x, out, nullptr, nullptr, nullptr, 512, 512);
}